// round 1
// baseline (speedup 1.0000x reference)
#include <cuda_runtime.h>
#include <math.h>

#define NNODES 50000
#define FEAT 128
#define HEADS 4
#define HIDC 32
#define OUTC 40
#define SLOPE 0.2f
#define MAXE 1100000

// ---------------- scratch (device globals; no allocation allowed) ----------------
__device__ __align__(16) int   g_cnt[NNODES];
__device__ __align__(16) int   g_rowptr[NNODES + 1];
__device__ __align__(16) int   g_cur[NNODES];
__device__ __align__(16) int   g_csr[MAXE];
__device__ __align__(16) float g_h[NNODES * FEAT];   // per-layer transformed features
__device__ __align__(16) float g_x[NNODES * FEAT];   // per-layer activations (next input)
__device__ __align__(16) float g_es[NNODES * HEADS];
__device__ __align__(16) float g_ed[NNODES * HEADS];
__device__ __align__(16) float g_h2[NNODES * OUTC];
__device__ __align__(16) float g_es2[NNODES];
__device__ __align__(16) float g_ed2[NNODES];

// ---------------- CSR build ----------------
__global__ void zero_cnt_kernel() {
    int i = blockIdx.x * blockDim.x + threadIdx.x;
    if (i < NNODES) g_cnt[i] = 0;
}

__global__ void count_kernel(const int* __restrict__ ei, int E) {
    int e = blockIdx.x * blockDim.x + threadIdx.x;
    if (e < E) atomicAdd(&g_cnt[ei[E + e]], 1);
}

__global__ void scan_kernel() {
    __shared__ int sh[1024];
    __shared__ int carry;
    int tid = threadIdx.x;
    if (tid == 0) carry = 0;
    __syncthreads();
    for (int base = 0; base < NNODES; base += 1024) {
        int i = base + tid;
        int v = (i < NNODES) ? (g_cnt[i] + 1) : 0;  // +1 = self loop
        sh[tid] = v;
        __syncthreads();
        for (int off = 1; off < 1024; off <<= 1) {
            int t = (tid >= off) ? sh[tid - off] : 0;
            __syncthreads();
            sh[tid] += t;
            __syncthreads();
        }
        int incl = sh[tid];
        int excl = carry + incl - v;
        if (i < NNODES) {
            g_rowptr[i] = excl;
            g_csr[excl] = i;       // self loop goes first in the row
            g_cur[i]    = excl + 1;
        }
        __syncthreads();
        if (tid == 0) carry += sh[1023];
        __syncthreads();
    }
    if (tid == 0) g_rowptr[NNODES] = carry;
}

__global__ void scatter_kernel(const int* __restrict__ ei, int E) {
    int e = blockIdx.x * blockDim.x + threadIdx.x;
    if (e < E) {
        int s = ei[e];
        int d = ei[E + e];
        int p = atomicAdd(&g_cur[d], 1);
        g_csr[p] = s;
    }
}

// ---------------- GEMM 128x128 + attention-logit epilogue ----------------
// grid: ceil(N/64) blocks, 256 threads. Tile: 64 nodes x 128 channels.
// Thread (ng = tid/32, cg = tid%32): nodes ng*8..ng*8+7, channels 4*cg..4*cg+3.
__global__ void gemm128_kernel(const float* __restrict__ xparam, int use_internal,
                               const float* __restrict__ W,
                               const float* __restrict__ avs,
                               const float* __restrict__ avd) {
    extern __shared__ float sm[];
    float* Ws = sm;                    // 128*128 floats
    float* Xs = sm + FEAT * FEAT;      // 64*128 floats
    const float* xin = use_internal ? g_x : xparam;

    int tid = threadIdx.x;
    int node0 = blockIdx.x * 64;

    float4* Ws4 = (float4*)Ws;
    const float4* W4 = (const float4*)W;
#pragma unroll
    for (int i = 0; i < 16; i++) Ws4[tid + i * 256] = W4[tid + i * 256];  // 4096 float4

    float4* Xs4 = (float4*)Xs;
    const float4* X4 = (const float4*)xin;
#pragma unroll
    for (int i = 0; i < 8; i++) {
        int idx = tid + i * 256;             // 0..2047
        int row = idx >> 5, c4 = idx & 31;
        int node = node0 + row;
        float4 v = make_float4(0.f, 0.f, 0.f, 0.f);
        if (node < NNODES) v = X4[node * 32 + c4];
        Xs4[idx] = v;
    }
    __syncthreads();

    int cg = tid & 31;
    int ng = tid >> 5;
    float acc[8][4];
#pragma unroll
    for (int i = 0; i < 8; i++) { acc[i][0] = acc[i][1] = acc[i][2] = acc[i][3] = 0.f; }

    const float* xbase = Xs + (ng * 8) * FEAT;
#pragma unroll 4
    for (int k = 0; k < FEAT; k++) {
        float4 w = Ws4[k * 32 + cg];
#pragma unroll
        for (int i = 0; i < 8; i++) {
            float xv = xbase[i * FEAT + k];   // broadcast within warp
            acc[i][0] += xv * w.x;
            acc[i][1] += xv * w.y;
            acc[i][2] += xv * w.z;
            acc[i][3] += xv * w.w;
        }
    }

    int head = cg >> 3, sub = cg & 7;
    float as0 = avs[head * HIDC + sub * 4 + 0], as1 = avs[head * HIDC + sub * 4 + 1];
    float as2 = avs[head * HIDC + sub * 4 + 2], as3 = avs[head * HIDC + sub * 4 + 3];
    float ad0 = avd[head * HIDC + sub * 4 + 0], ad1 = avd[head * HIDC + sub * 4 + 1];
    float ad2 = avd[head * HIDC + sub * 4 + 2], ad3 = avd[head * HIDC + sub * 4 + 3];

    float4* H4 = (float4*)g_h;
#pragma unroll
    for (int i = 0; i < 8; i++) {
        int node = node0 + ng * 8 + i;
        float pes = acc[i][0] * as0 + acc[i][1] * as1 + acc[i][2] * as2 + acc[i][3] * as3;
        float ped = acc[i][0] * ad0 + acc[i][1] * ad1 + acc[i][2] * ad2 + acc[i][3] * ad3;
#pragma unroll
        for (int off = 1; off < 8; off <<= 1) {
            pes += __shfl_xor_sync(0xffffffffu, pes, off);
            ped += __shfl_xor_sync(0xffffffffu, ped, off);
        }
        if (node < NNODES) {
            H4[node * 32 + cg] = make_float4(acc[i][0], acc[i][1], acc[i][2], acc[i][3]);
            if (sub == 0) {
                g_es[node * HEADS + head] = pes;
                g_ed[node * HEADS + head] = ped;
            }
        }
    }
}

// ---------------- Aggregation, layers 0/1: warp per dst node ----------------
__global__ void agg_kernel(const float* __restrict__ bias, int do_elu) {
    int warp = (blockIdx.x * blockDim.x + threadIdx.x) >> 5;
    int lane = threadIdx.x & 31;
    if (warp >= NNODES) return;
    int n = warp;
    int r0 = g_rowptr[n], r1 = g_rowptr[n + 1];

    const float4* ES4 = (const float4*)g_es;
    float4 edq = ((const float4*)g_ed)[n];

    // pass A: per-head max of leaky(es[src]+ed[dst])
    float m0 = -1e30f, m1 = -1e30f, m2 = -1e30f, m3 = -1e30f;
    for (int idx = r0 + lane; idx < r1; idx += 32) {
        int s = g_csr[idx];
        float4 esq = ES4[s];
        float e0 = esq.x + edq.x; e0 = e0 > 0.f ? e0 : SLOPE * e0;
        float e1 = esq.y + edq.y; e1 = e1 > 0.f ? e1 : SLOPE * e1;
        float e2 = esq.z + edq.z; e2 = e2 > 0.f ? e2 : SLOPE * e2;
        float e3 = esq.w + edq.w; e3 = e3 > 0.f ? e3 : SLOPE * e3;
        m0 = fmaxf(m0, e0); m1 = fmaxf(m1, e1); m2 = fmaxf(m2, e2); m3 = fmaxf(m3, e3);
    }
#pragma unroll
    for (int off = 16; off; off >>= 1) {
        m0 = fmaxf(m0, __shfl_xor_sync(0xffffffffu, m0, off));
        m1 = fmaxf(m1, __shfl_xor_sync(0xffffffffu, m1, off));
        m2 = fmaxf(m2, __shfl_xor_sync(0xffffffffu, m2, off));
        m3 = fmaxf(m3, __shfl_xor_sync(0xffffffffu, m3, off));
    }

    int hl = lane >> 3;   // head of this lane's 4 channels (c = 4*lane..4*lane+3)
    float mh  = (hl == 0) ? m0 : (hl == 1) ? m1 : (hl == 2) ? m2 : m3;
    float edh = (hl == 0) ? edq.x : (hl == 1) ? edq.y : (hl == 2) ? edq.z : edq.w;

    // pass B: weighted accumulation (no atomics, all in registers)
    float a0 = 0.f, a1 = 0.f, a2 = 0.f, a3 = 0.f, wsum = 0.f;
    const float4* H4 = (const float4*)g_h;
    for (int base = r0; base < r1; base += 32) {
        int cnt = min(32, r1 - base);
        int sv = 0;
        if (lane < cnt) sv = g_csr[base + lane];
        for (int j = 0; j < cnt; j++) {
            int s = __shfl_sync(0xffffffffu, sv, j);
            float e = g_es[s * HEADS + hl] + edh;
            e = e > 0.f ? e : SLOPE * e;
            float w = __expf(e - mh);
            wsum += w;
            float4 hv = H4[s * 32 + lane];
            a0 += w * hv.x; a1 += w * hv.y; a2 += w * hv.z; a3 += w * hv.w;
        }
    }

    float inv = 1.f / (wsum + 1e-16f);
    int c0 = lane * 4;
    float v0 = a0 * inv + bias[c0 + 0];
    float v1 = a1 * inv + bias[c0 + 1];
    float v2 = a2 * inv + bias[c0 + 2];
    float v3 = a3 * inv + bias[c0 + 3];
    if (do_elu) {
        v0 = v0 > 0.f ? v0 : expm1f(v0);
        v1 = v1 > 0.f ? v1 : expm1f(v1);
        v2 = v2 > 0.f ? v2 : expm1f(v2);
        v3 = v3 > 0.f ? v3 : expm1f(v3);
    }
    ((float4*)g_x)[n * 32 + lane] = make_float4(v0, v1, v2, v3);
}

// ---------------- Layer 2 GEMM (128 -> 40) + logit epilogue ----------------
__global__ void gemm2_kernel(const float* __restrict__ W,
                             const float* __restrict__ avs,
                             const float* __restrict__ avd) {
    __shared__ float Ws[FEAT * OUTC];  // 20 KB
    int tid = threadIdx.x;
    for (int i = tid; i < FEAT * OUTC; i += blockDim.x) Ws[i] = W[i];
    __syncthreads();

    int warp = tid >> 5, lane = tid & 31;
    int n = blockIdx.x * 8 + warp;
    if (n >= NNODES) return;

    float xr[4];
#pragma unroll
    for (int j = 0; j < 4; j++) xr[j] = g_x[n * FEAT + j * 32 + lane];

    float acc0 = 0.f, acc1 = 0.f;
#pragma unroll
    for (int k = 0; k < FEAT; k++) {
        float xv = __shfl_sync(0xffffffffu, xr[k >> 5], k & 31);
        acc0 += xv * Ws[k * OUTC + lane];
        if (lane < 8) acc1 += xv * Ws[k * OUTC + 32 + lane];
    }

    g_h2[n * OUTC + lane] = acc0;
    if (lane < 8) g_h2[n * OUTC + 32 + lane] = acc1;

    float pes = acc0 * avs[lane] + ((lane < 8) ? acc1 * avs[32 + lane] : 0.f);
    float ped = acc0 * avd[lane] + ((lane < 8) ? acc1 * avd[32 + lane] : 0.f);
#pragma unroll
    for (int off = 16; off; off >>= 1) {
        pes += __shfl_xor_sync(0xffffffffu, pes, off);
        ped += __shfl_xor_sync(0xffffffffu, ped, off);
    }
    if (lane == 0) { g_es2[n] = pes; g_ed2[n] = ped; }
}

// ---------------- Layer 2 aggregation + log_softmax ----------------
__global__ void agg2_kernel(const float* __restrict__ bias, float* __restrict__ out) {
    int warp = (blockIdx.x * blockDim.x + threadIdx.x) >> 5;
    int lane = threadIdx.x & 31;
    if (warp >= NNODES) return;
    int n = warp;
    int r0 = g_rowptr[n], r1 = g_rowptr[n + 1];
    float edn = g_ed2[n];

    float m = -1e30f;
    for (int idx = r0 + lane; idx < r1; idx += 32) {
        int s = g_csr[idx];
        float e = g_es2[s] + edn;
        e = e > 0.f ? e : SLOPE * e;
        m = fmaxf(m, e);
    }
#pragma unroll
    for (int off = 16; off; off >>= 1)
        m = fmaxf(m, __shfl_xor_sync(0xffffffffu, m, off));

    float acc0 = 0.f, acc1 = 0.f, wsum = 0.f;
    for (int base = r0; base < r1; base += 32) {
        int cnt = min(32, r1 - base);
        int sv = 0;
        if (lane < cnt) sv = g_csr[base + lane];
        for (int j = 0; j < cnt; j++) {
            int s = __shfl_sync(0xffffffffu, sv, j);
            float e = g_es2[s] + edn;
            e = e > 0.f ? e : SLOPE * e;
            float w = __expf(e - m);
            wsum += w;
            acc0 += w * g_h2[s * OUTC + lane];
            if (lane < 8) acc1 += w * g_h2[s * OUTC + 32 + lane];
        }
    }

    float inv = 1.f / (wsum + 1e-16f);
    float v0 = acc0 * inv + bias[lane];
    float v1 = (lane < 8) ? (acc1 * inv + bias[32 + lane]) : -1e30f;

    float mx = fmaxf(v0, v1);
#pragma unroll
    for (int off = 16; off; off >>= 1)
        mx = fmaxf(mx, __shfl_xor_sync(0xffffffffu, mx, off));

    float se = expf(v0 - mx) + ((lane < 8) ? expf(v1 - mx) : 0.f);
#pragma unroll
    for (int off = 16; off; off >>= 1)
        se += __shfl_xor_sync(0xffffffffu, se, off);

    float lse = mx + logf(se);
    out[n * OUTC + lane] = v0 - lse;
    if (lane < 8) out[n * OUTC + 32 + lane] = v1 - lse;
}

// ---------------- launch ----------------
extern "C" void kernel_launch(void* const* d_in, const int* in_sizes, int n_in,
                              void* d_out, int out_size) {
    const float* x   = (const float*)d_in[0];
    const int*   ei  = (const int*)d_in[1];
    const float* W0  = (const float*)d_in[2];
    const float* as0 = (const float*)d_in[3];
    const float* ad0 = (const float*)d_in[4];
    const float* b0  = (const float*)d_in[5];
    const float* W1  = (const float*)d_in[6];
    const float* as1 = (const float*)d_in[7];
    const float* ad1 = (const float*)d_in[8];
    const float* b1  = (const float*)d_in[9];
    const float* W2  = (const float*)d_in[10];
    const float* as2 = (const float*)d_in[11];
    const float* ad2 = (const float*)d_in[12];
    const float* b2  = (const float*)d_in[13];
    float* out = (float*)d_out;

    int E = in_sizes[1] / 2;
    if (E + NNODES > MAXE) return;  // capacity guard (never hit for this problem)

    const int GSM = (FEAT * FEAT + 64 * FEAT) * 4;  // 96 KB dynamic smem
    cudaFuncSetAttribute(gemm128_kernel, cudaFuncAttributeMaxDynamicSharedMemorySize, GSM);

    // CSR build
    zero_cnt_kernel<<<(NNODES + 255) / 256, 256>>>();
    count_kernel<<<(E + 255) / 256, 256>>>(ei, E);
    scan_kernel<<<1, 1024>>>();
    scatter_kernel<<<(E + 255) / 256, 256>>>(ei, E);

    int gemm_grid = (NNODES + 63) / 64;
    int agg_grid  = (NNODES + 7) / 8;

    // layer 0
    gemm128_kernel<<<gemm_grid, 256, GSM>>>(x, 0, W0, as0, ad0);
    agg_kernel<<<agg_grid, 256>>>(b0, 1);
    // layer 1
    gemm128_kernel<<<gemm_grid, 256, GSM>>>(nullptr, 1, W1, as1, ad1);
    agg_kernel<<<agg_grid, 256>>>(b1, 1);
    // layer 2
    gemm2_kernel<<<agg_grid, 256>>>(W2, as2, ad2);
    agg2_kernel<<<agg_grid, 256>>>(b2, out);
}

// round 2
// speedup vs baseline: 1.2617x; 1.2617x over previous
#include <cuda_runtime.h>
#include <math.h>

#define NNODES 50000
#define FEAT 128
#define HEADS 4
#define HIDC 32
#define OUTC 40
#define SLOPE 0.2f
#define MAXE 1100000
#define NB 196            // ceil(NNODES/256)

// ---------------- scratch (device globals; no allocation allowed) ----------------
__device__ __align__(16) int   g_cnt[NNODES];
__device__ __align__(16) int   g_rowptr[NNODES + 1];
__device__ __align__(16) int   g_cur[NNODES];
__device__ __align__(16) int   g_csr[MAXE];
__device__ __align__(16) int   g_part[NB];
__device__ __align__(16) float g_h[NNODES * FEAT];   // per-layer transformed features
__device__ __align__(16) float g_x[NNODES * FEAT];   // per-layer activations (next input)
__device__ __align__(16) float g_es[NNODES * HEADS];
__device__ __align__(16) float g_ed[NNODES * HEADS];
__device__ __align__(16) float g_h2[NNODES * OUTC];
__device__ __align__(16) float g_es2[NNODES];
__device__ __align__(16) float g_ed2[NNODES];

// ---------------- f32x2 packed math helpers ----------------
__device__ __forceinline__ void ffma2(unsigned long long& d, unsigned long long a,
                                      unsigned long long b) {
    asm volatile("fma.rn.f32x2 %0, %1, %2, %0;" : "+l"(d) : "l"(a), "l"(b));
}
__device__ __forceinline__ unsigned long long pack2(float x) {
    unsigned long long r;
    asm("mov.b64 %0, {%1, %1};" : "=l"(r) : "f"(x));
    return r;
}
__device__ __forceinline__ float2 unpack2(unsigned long long v) {
    float2 r;
    asm("mov.b64 {%0, %1}, %2;" : "=f"(r.x), "=f"(r.y) : "l"(v));
    return r;
}

// ---------------- CSR build ----------------
__global__ void zero_cnt_kernel() {
    int i = blockIdx.x * blockDim.x + threadIdx.x;
    if (i < NNODES) g_cnt[i] = 0;
}

__global__ void count_kernel(const int* __restrict__ ei, int E) {
    int e = blockIdx.x * blockDim.x + threadIdx.x;
    if (e < E) atomicAdd(&g_cnt[ei[E + e]], 1);
}

// block sums of (cnt+1)
__global__ void blocksum_kernel() {
    int b = blockIdx.x, tid = threadIdx.x, lane = tid & 31, w = tid >> 5;
    int i = b * 256 + tid;
    int v = (i < NNODES) ? (g_cnt[i] + 1) : 0;
#pragma unroll
    for (int off = 16; off; off >>= 1) v += __shfl_xor_sync(0xffffffffu, v, off);
    __shared__ int ws[8];
    if (lane == 0) ws[w] = v;
    __syncthreads();
    if (tid == 0) {
        int s = 0;
#pragma unroll
        for (int k = 0; k < 8; k++) s += ws[k];
        g_part[b] = s;
    }
}

// exclusive scan of the NB partials (single block)
__global__ void scanpart_kernel() {
    int tid = threadIdx.x, lane = tid & 31, w = tid >> 5;
    int v = (tid < NB) ? g_part[tid] : 0;
    int orig = v;
#pragma unroll
    for (int off = 1; off < 32; off <<= 1) {
        int t = __shfl_up_sync(0xffffffffu, v, off);
        if (lane >= off) v += t;
    }
    __shared__ int ws[8];
    if (lane == 31) ws[w] = v;
    __syncthreads();
    if (tid == 0) {
        int run = 0;
#pragma unroll
        for (int k = 0; k < 8; k++) { int t = ws[k]; ws[k] = run; run += t; }
        g_rowptr[NNODES] = run;   // total edge count incl self loops
    }
    __syncthreads();
    int incl = v + ws[w];
    if (tid < NB) g_part[tid] = incl - orig;   // exclusive prefix
}

// per-block rescan + emit rowptr / self-loop / cursors
__global__ void rowptr_kernel() {
    int b = blockIdx.x, tid = threadIdx.x, lane = tid & 31, w = tid >> 5;
    int i = b * 256 + tid;
    int v = (i < NNODES) ? (g_cnt[i] + 1) : 0;
    int orig = v;
#pragma unroll
    for (int off = 1; off < 32; off <<= 1) {
        int t = __shfl_up_sync(0xffffffffu, v, off);
        if (lane >= off) v += t;
    }
    __shared__ int ws[8];
    if (lane == 31) ws[w] = v;
    __syncthreads();
    if (tid == 0) {
        int run = 0;
#pragma unroll
        for (int k = 0; k < 8; k++) { int t = ws[k]; ws[k] = run; run += t; }
    }
    __syncthreads();
    int excl = v - orig + ws[w] + g_part[b];
    if (i < NNODES) {
        g_rowptr[i] = excl;
        g_csr[excl] = i;     // self loop first in row
        g_cur[i]    = excl + 1;
    }
}

__global__ void scatter_kernel(const int* __restrict__ ei, int E) {
    int e = blockIdx.x * blockDim.x + threadIdx.x;
    if (e < E) {
        int s = ei[e];
        int d = ei[E + e];
        int p = atomicAdd(&g_cur[d], 1);
        g_csr[p] = s;
    }
}

// ---------------- GEMM 128x128 (f32x2 packed) + attention-logit epilogue ----------------
// grid: ceil(N/64) blocks, 256 threads. Tile: 64 nodes x 128 channels.
// Thread (ng = tid/32, cg = tid%32): nodes ng*8..ng*8+7, channels 4*cg..4*cg+3.
__global__ void gemm128_kernel(const float* __restrict__ xparam, int use_internal,
                               const float* __restrict__ W,
                               const float* __restrict__ avs,
                               const float* __restrict__ avd) {
    extern __shared__ float sm[];
    float* Ws = sm;                    // 128*128 floats
    float* Xs = sm + FEAT * FEAT;      // 64*128 floats
    const float* xin = use_internal ? g_x : xparam;

    int tid = threadIdx.x;
    int node0 = blockIdx.x * 64;

    float4* Ws4 = (float4*)Ws;
    const float4* W4 = (const float4*)W;
#pragma unroll
    for (int i = 0; i < 16; i++) Ws4[tid + i * 256] = W4[tid + i * 256];

    float4* Xs4 = (float4*)Xs;
    const float4* X4 = (const float4*)xin;
#pragma unroll
    for (int i = 0; i < 8; i++) {
        int idx = tid + i * 256;
        int row = idx >> 5, c4 = idx & 31;
        int node = node0 + row;
        float4 v = make_float4(0.f, 0.f, 0.f, 0.f);
        if (node < NNODES) v = X4[node * 32 + c4];
        Xs4[idx] = v;
    }
    __syncthreads();

    int cg = tid & 31;
    int ng = tid >> 5;
    unsigned long long acc[8][2];
#pragma unroll
    for (int i = 0; i < 8; i++) { acc[i][0] = 0ull; acc[i][1] = 0ull; }

    const float* xbase = Xs + (ng * 8) * FEAT;
    const ulonglong2* Ws2 = (const ulonglong2*)Ws;
#pragma unroll 4
    for (int k = 0; k < FEAT; k++) {
        ulonglong2 w = Ws2[k * 32 + cg];    // (w.x,w.y),(w.z,w.w) as packed pairs
#pragma unroll
        for (int i = 0; i < 8; i++) {
            unsigned long long xx = pack2(xbase[i * FEAT + k]);  // warp-broadcast LDS
            ffma2(acc[i][0], xx, w.x);
            ffma2(acc[i][1], xx, w.y);
        }
    }

    int head = cg >> 3, sub = cg & 7;
    float as0 = avs[head * HIDC + sub * 4 + 0], as1 = avs[head * HIDC + sub * 4 + 1];
    float as2 = avs[head * HIDC + sub * 4 + 2], as3 = avs[head * HIDC + sub * 4 + 3];
    float ad0 = avd[head * HIDC + sub * 4 + 0], ad1 = avd[head * HIDC + sub * 4 + 1];
    float ad2 = avd[head * HIDC + sub * 4 + 2], ad3 = avd[head * HIDC + sub * 4 + 3];

    float4* H4 = (float4*)g_h;
#pragma unroll
    for (int i = 0; i < 8; i++) {
        int node = node0 + ng * 8 + i;
        float2 p0 = unpack2(acc[i][0]);
        float2 p1 = unpack2(acc[i][1]);
        float pes = p0.x * as0 + p0.y * as1 + p1.x * as2 + p1.y * as3;
        float ped = p0.x * ad0 + p0.y * ad1 + p1.x * ad2 + p1.y * ad3;
#pragma unroll
        for (int off = 1; off < 8; off <<= 1) {
            pes += __shfl_xor_sync(0xffffffffu, pes, off);
            ped += __shfl_xor_sync(0xffffffffu, ped, off);
        }
        if (node < NNODES) {
            H4[node * 32 + cg] = make_float4(p0.x, p0.y, p1.x, p1.y);
            if (sub == 0) {
                g_es[node * HEADS + head] = pes;
                g_ed[node * HEADS + head] = ped;
            }
        }
    }
}

// ---------------- Aggregation, layers 0/1: warp per dst node, single pass ----------------
// exp without max-subtraction: logits bounded (|e| < ~15), mathematically identical alpha.
__global__ void agg_kernel(const float* __restrict__ bias, int do_elu) {
    int warp = (blockIdx.x * blockDim.x + threadIdx.x) >> 5;
    int lane = threadIdx.x & 31;
    if (warp >= NNODES) return;
    int n = warp;
    int r0 = g_rowptr[n], r1 = g_rowptr[n + 1];

    const float4* ES4 = (const float4*)g_es;
    float4 edq = ((const float4*)g_ed)[n];
    int hl = lane >> 3;   // head owning channels 4*lane..4*lane+3
    float edh = (hl == 0) ? edq.x : (hl == 1) ? edq.y : (hl == 2) ? edq.z : edq.w;

    float a0 = 0.f, a1 = 0.f, a2 = 0.f, a3 = 0.f, wsum = 0.f;
    const float4* H4 = (const float4*)g_h;
    for (int base = r0; base < r1; base += 32) {
        int cnt = min(32, r1 - base);
        int sv = 0;
        if (lane < cnt) sv = g_csr[base + lane];
        for (int j = 0; j < cnt; j++) {
            int s = __shfl_sync(0xffffffffu, sv, j);
            float4 esq = ES4[s];     // warp-broadcast
            float es = (hl == 0) ? esq.x : (hl == 1) ? esq.y : (hl == 2) ? esq.z : esq.w;
            float e = es + edh;
            e = e > 0.f ? e : SLOPE * e;
            float w = __expf(e);
            wsum += w;
            float4 hv = H4[s * 32 + lane];
            a0 += w * hv.x; a1 += w * hv.y; a2 += w * hv.z; a3 += w * hv.w;
        }
    }

    float inv = 1.f / (wsum + 1e-16f);
    int c0 = lane * 4;
    float v0 = a0 * inv + bias[c0 + 0];
    float v1 = a1 * inv + bias[c0 + 1];
    float v2 = a2 * inv + bias[c0 + 2];
    float v3 = a3 * inv + bias[c0 + 3];
    if (do_elu) {
        v0 = v0 > 0.f ? v0 : expm1f(v0);
        v1 = v1 > 0.f ? v1 : expm1f(v1);
        v2 = v2 > 0.f ? v2 : expm1f(v2);
        v3 = v3 > 0.f ? v3 : expm1f(v3);
    }
    ((float4*)g_x)[n * 32 + lane] = make_float4(v0, v1, v2, v3);
}

// ---------------- Layer 2 GEMM (128 -> 40) + logit epilogue ----------------
__global__ void gemm2_kernel(const float* __restrict__ W,
                             const float* __restrict__ avs,
                             const float* __restrict__ avd) {
    __shared__ float Ws[FEAT * OUTC];  // 20 KB
    int tid = threadIdx.x;
    for (int i = tid; i < FEAT * OUTC; i += blockDim.x) Ws[i] = W[i];
    __syncthreads();

    int warp = tid >> 5, lane = tid & 31;
    int n = blockIdx.x * 8 + warp;
    if (n >= NNODES) return;

    float xr[4];
#pragma unroll
    for (int j = 0; j < 4; j++) xr[j] = g_x[n * FEAT + j * 32 + lane];

    float acc0 = 0.f, acc1 = 0.f;
#pragma unroll
    for (int k = 0; k < FEAT; k++) {
        float xv = __shfl_sync(0xffffffffu, xr[k >> 5], k & 31);
        acc0 += xv * Ws[k * OUTC + lane];
        if (lane < 8) acc1 += xv * Ws[k * OUTC + 32 + lane];
    }

    g_h2[n * OUTC + lane] = acc0;
    if (lane < 8) g_h2[n * OUTC + 32 + lane] = acc1;

    float pes = acc0 * avs[lane] + ((lane < 8) ? acc1 * avs[32 + lane] : 0.f);
    float ped = acc0 * avd[lane] + ((lane < 8) ? acc1 * avd[32 + lane] : 0.f);
#pragma unroll
    for (int off = 16; off; off >>= 1) {
        pes += __shfl_xor_sync(0xffffffffu, pes, off);
        ped += __shfl_xor_sync(0xffffffffu, ped, off);
    }
    if (lane == 0) { g_es2[n] = pes; g_ed2[n] = ped; }
}

// ---------------- Layer 2 aggregation + log_softmax (single pass) ----------------
__global__ void agg2_kernel(const float* __restrict__ bias, float* __restrict__ out) {
    int warp = (blockIdx.x * blockDim.x + threadIdx.x) >> 5;
    int lane = threadIdx.x & 31;
    if (warp >= NNODES) return;
    int n = warp;
    int r0 = g_rowptr[n], r1 = g_rowptr[n + 1];
    float edn = g_ed2[n];

    float acc0 = 0.f, acc1 = 0.f, wsum = 0.f;
    for (int base = r0; base < r1; base += 32) {
        int cnt = min(32, r1 - base);
        int sv = 0;
        if (lane < cnt) sv = g_csr[base + lane];
        for (int j = 0; j < cnt; j++) {
            int s = __shfl_sync(0xffffffffu, sv, j);
            float e = g_es2[s] + edn;
            e = e > 0.f ? e : SLOPE * e;
            float w = __expf(e);
            wsum += w;
            acc0 += w * g_h2[s * OUTC + lane];
            if (lane < 8) acc1 += w * g_h2[s * OUTC + 32 + lane];
        }
    }

    float inv = 1.f / (wsum + 1e-16f);
    float v0 = acc0 * inv + bias[lane];
    float v1 = (lane < 8) ? (acc1 * inv + bias[32 + lane]) : -1e30f;

    // log_softmax over the 40 class logits (keep this max: different purpose)
    float mx = fmaxf(v0, v1);
#pragma unroll
    for (int off = 16; off; off >>= 1)
        mx = fmaxf(mx, __shfl_xor_sync(0xffffffffu, mx, off));

    float se = expf(v0 - mx) + ((lane < 8) ? expf(v1 - mx) : 0.f);
#pragma unroll
    for (int off = 16; off; off >>= 1)
        se += __shfl_xor_sync(0xffffffffu, se, off);

    float lse = mx + logf(se);
    out[n * OUTC + lane] = v0 - lse;
    if (lane < 8) out[n * OUTC + 32 + lane] = v1 - lse;
}

// ---------------- launch ----------------
extern "C" void kernel_launch(void* const* d_in, const int* in_sizes, int n_in,
                              void* d_out, int out_size) {
    const float* x   = (const float*)d_in[0];
    const int*   ei  = (const int*)d_in[1];
    const float* W0  = (const float*)d_in[2];
    const float* as0 = (const float*)d_in[3];
    const float* ad0 = (const float*)d_in[4];
    const float* b0  = (const float*)d_in[5];
    const float* W1  = (const float*)d_in[6];
    const float* as1 = (const float*)d_in[7];
    const float* ad1 = (const float*)d_in[8];
    const float* b1  = (const float*)d_in[9];
    const float* W2  = (const float*)d_in[10];
    const float* as2 = (const float*)d_in[11];
    const float* ad2 = (const float*)d_in[12];
    const float* b2  = (const float*)d_in[13];
    float* out = (float*)d_out;

    int E = in_sizes[1] / 2;
    if (E + NNODES > MAXE) return;  // capacity guard (never hit for this problem)

    const int GSM = (FEAT * FEAT + 64 * FEAT) * 4;  // 96 KB dynamic smem
    cudaFuncSetAttribute(gemm128_kernel, cudaFuncAttributeMaxDynamicSharedMemorySize, GSM);

    // CSR build (2-level parallel scan)
    zero_cnt_kernel<<<(NNODES + 255) / 256, 256>>>();
    count_kernel<<<(E + 255) / 256, 256>>>(ei, E);
    blocksum_kernel<<<NB, 256>>>();
    scanpart_kernel<<<1, 256>>>();
    rowptr_kernel<<<NB, 256>>>();
    scatter_kernel<<<(E + 255) / 256, 256>>>(ei, E);

    int gemm_grid = (NNODES + 63) / 64;
    int agg_grid  = (NNODES + 7) / 8;

    // layer 0
    gemm128_kernel<<<gemm_grid, 256, GSM>>>(x, 0, W0, as0, ad0);
    agg_kernel<<<agg_grid, 256>>>(b0, 1);
    // layer 1
    gemm128_kernel<<<gemm_grid, 256, GSM>>>(nullptr, 1, W1, as1, ad1);
    agg_kernel<<<agg_grid, 256>>>(b1, 1);
    // layer 2
    gemm2_kernel<<<agg_grid, 256>>>(W2, as2, ad2);
    agg2_kernel<<<agg_grid, 256>>>(b2, out);
}

// round 3
// speedup vs baseline: 1.3596x; 1.0776x over previous
#include <cuda_runtime.h>
#include <cuda_fp16.h>
#include <math.h>

#define NNODES 50000
#define FEAT 128
#define HEADS 4
#define HIDC 32
#define OUTC 40
#define SLOPE 0.2f
#define MAXE 1100000
#define NB 196            // ceil(NNODES/256)

// ---------------- scratch (device globals; no allocation allowed) ----------------
__device__ __align__(16) int   g_cnt[NNODES];
__device__ __align__(16) int   g_rowptr[NNODES + 1];
__device__ __align__(16) int   g_cur[NNODES];
__device__ __align__(16) int   g_csr[MAXE];
__device__ __align__(16) int   g_part[NB];
__device__ __align__(16) unsigned int g_hh[NNODES * 64];   // fp16 messages: 128 half per node
__device__ __align__(16) float g_x[NNODES * FEAT];         // fp32 activations (next input)
__device__ __align__(16) float g_es[NNODES * HEADS];
__device__ __align__(16) float g_ed[NNODES * HEADS];
__device__ __align__(16) float g_h2[NNODES * OUTC];
__device__ __align__(16) float g_es2[NNODES];
__device__ __align__(16) float g_ed2[NNODES];

// ---------------- f32x2 packed math helpers ----------------
__device__ __forceinline__ void ffma2(unsigned long long& d, unsigned long long a,
                                      unsigned long long b) {
    asm volatile("fma.rn.f32x2 %0, %1, %2, %0;" : "+l"(d) : "l"(a), "l"(b));
}
__device__ __forceinline__ unsigned long long pack2(float x) {
    unsigned long long r;
    asm("mov.b64 %0, {%1, %1};" : "=l"(r) : "f"(x));
    return r;
}
__device__ __forceinline__ float2 unpack2(unsigned long long v) {
    float2 r;
    asm("mov.b64 {%0, %1}, %2;" : "=f"(r.x), "=f"(r.y) : "l"(v));
    return r;
}

// ---------------- CSR build ----------------
__global__ void zero_cnt_kernel() {
    int i = blockIdx.x * blockDim.x + threadIdx.x;
    if (i < NNODES) g_cnt[i] = 0;
}

__global__ void count_kernel(const int* __restrict__ ei, int E) {
    int e = blockIdx.x * blockDim.x + threadIdx.x;
    if (e < E) atomicAdd(&g_cnt[ei[E + e]], 1);
}

__global__ void blocksum_kernel() {
    int b = blockIdx.x, tid = threadIdx.x, lane = tid & 31, w = tid >> 5;
    int i = b * 256 + tid;
    int v = (i < NNODES) ? (g_cnt[i] + 1) : 0;
#pragma unroll
    for (int off = 16; off; off >>= 1) v += __shfl_xor_sync(0xffffffffu, v, off);
    __shared__ int ws[8];
    if (lane == 0) ws[w] = v;
    __syncthreads();
    if (tid == 0) {
        int s = 0;
#pragma unroll
        for (int k = 0; k < 8; k++) s += ws[k];
        g_part[b] = s;
    }
}

__global__ void scanpart_kernel() {
    int tid = threadIdx.x, lane = tid & 31, w = tid >> 5;
    int v = (tid < NB) ? g_part[tid] : 0;
    int orig = v;
#pragma unroll
    for (int off = 1; off < 32; off <<= 1) {
        int t = __shfl_up_sync(0xffffffffu, v, off);
        if (lane >= off) v += t;
    }
    __shared__ int ws[8];
    if (lane == 31) ws[w] = v;
    __syncthreads();
    if (tid == 0) {
        int run = 0;
#pragma unroll
        for (int k = 0; k < 8; k++) { int t = ws[k]; ws[k] = run; run += t; }
        g_rowptr[NNODES] = run;
    }
    __syncthreads();
    int incl = v + ws[w];
    if (tid < NB) g_part[tid] = incl - orig;
}

__global__ void rowptr_kernel() {
    int b = blockIdx.x, tid = threadIdx.x, lane = tid & 31, w = tid >> 5;
    int i = b * 256 + tid;
    int v = (i < NNODES) ? (g_cnt[i] + 1) : 0;
    int orig = v;
#pragma unroll
    for (int off = 1; off < 32; off <<= 1) {
        int t = __shfl_up_sync(0xffffffffu, v, off);
        if (lane >= off) v += t;
    }
    __shared__ int ws[8];
    if (lane == 31) ws[w] = v;
    __syncthreads();
    if (tid == 0) {
        int run = 0;
#pragma unroll
        for (int k = 0; k < 8; k++) { int t = ws[k]; ws[k] = run; run += t; }
    }
    __syncthreads();
    int excl = v - orig + ws[w] + g_part[b];
    if (i < NNODES) {
        g_rowptr[i] = excl;
        g_csr[excl] = i;     // self loop first in row
        g_cur[i]    = excl + 1;
    }
}

__global__ void scatter_kernel(const int* __restrict__ ei, int E) {
    int e = blockIdx.x * blockDim.x + threadIdx.x;
    if (e < E) {
        int s = ei[e];
        int d = ei[E + e];
        int p = atomicAdd(&g_cur[d], 1);
        g_csr[p] = s;
    }
}

// ---------------- GEMM 128x128 (f32x2 packed) + fp16 store + logit epilogue --------
__global__ void gemm128_kernel(const float* __restrict__ xparam, int use_internal,
                               const float* __restrict__ W,
                               const float* __restrict__ avs,
                               const float* __restrict__ avd) {
    extern __shared__ float sm[];
    float* Ws = sm;                    // 128*128 floats
    float* Xs = sm + FEAT * FEAT;      // 64*128 floats
    const float* xin = use_internal ? g_x : xparam;

    int tid = threadIdx.x;
    int node0 = blockIdx.x * 64;

    float4* Ws4 = (float4*)Ws;
    const float4* W4 = (const float4*)W;
#pragma unroll
    for (int i = 0; i < 16; i++) Ws4[tid + i * 256] = W4[tid + i * 256];

    float4* Xs4 = (float4*)Xs;
    const float4* X4 = (const float4*)xin;
#pragma unroll
    for (int i = 0; i < 8; i++) {
        int idx = tid + i * 256;
        int row = idx >> 5, c4 = idx & 31;
        int node = node0 + row;
        float4 v = make_float4(0.f, 0.f, 0.f, 0.f);
        if (node < NNODES) v = X4[node * 32 + c4];
        Xs4[idx] = v;
    }
    __syncthreads();

    int cg = tid & 31;
    int ng = tid >> 5;
    unsigned long long acc[8][2];
#pragma unroll
    for (int i = 0; i < 8; i++) { acc[i][0] = 0ull; acc[i][1] = 0ull; }

    const float* xbase = Xs + (ng * 8) * FEAT;
    const ulonglong2* Ws2 = (const ulonglong2*)Ws;
#pragma unroll 4
    for (int k = 0; k < FEAT; k++) {
        ulonglong2 w = Ws2[k * 32 + cg];
#pragma unroll
        for (int i = 0; i < 8; i++) {
            unsigned long long xx = pack2(xbase[i * FEAT + k]);
            ffma2(acc[i][0], xx, w.x);
            ffma2(acc[i][1], xx, w.y);
        }
    }

    int head = cg >> 3, sub = cg & 7;
    float as0 = avs[head * HIDC + sub * 4 + 0], as1 = avs[head * HIDC + sub * 4 + 1];
    float as2 = avs[head * HIDC + sub * 4 + 2], as3 = avs[head * HIDC + sub * 4 + 3];
    float ad0 = avd[head * HIDC + sub * 4 + 0], ad1 = avd[head * HIDC + sub * 4 + 1];
    float ad2 = avd[head * HIDC + sub * 4 + 2], ad3 = avd[head * HIDC + sub * 4 + 3];

    uint2* HH2 = (uint2*)g_hh;
#pragma unroll
    for (int i = 0; i < 8; i++) {
        int node = node0 + ng * 8 + i;
        float2 p0 = unpack2(acc[i][0]);
        float2 p1 = unpack2(acc[i][1]);
        float pes = p0.x * as0 + p0.y * as1 + p1.x * as2 + p1.y * as3;
        float ped = p0.x * ad0 + p0.y * ad1 + p1.x * ad2 + p1.y * ad3;
#pragma unroll
        for (int off = 1; off < 8; off <<= 1) {
            pes += __shfl_xor_sync(0xffffffffu, pes, off);
            ped += __shfl_xor_sync(0xffffffffu, ped, off);
        }
        if (node < NNODES) {
            __half2 hlo = __floats2half2_rn(p0.x, p0.y);
            __half2 hhi = __floats2half2_rn(p1.x, p1.y);
            uint2 hv;
            hv.x = *(unsigned int*)&hlo;
            hv.y = *(unsigned int*)&hhi;
            HH2[node * 32 + cg] = hv;
            if (sub == 0) {
                g_es[node * HEADS + head] = pes;
                g_ed[node * HEADS + head] = ped;
            }
        }
    }
}

// ---------------- Aggregation, layers 0/1: warp per dst node ----------------
// Per-batch: each lane computes its edge's 4 head-weights once (1 exp per head
// per edge total, not per consumer lane), stages src + weights in smem.
// Inner loop per edge: 2 broadcast LDS + 8B LDG + 4 FMA, unrolled for MLP.
__global__ void agg_kernel(const float* __restrict__ bias, int do_elu) {
    __shared__ float4 sw[8][32];
    __shared__ int    ss[8][32];
    int tid = threadIdx.x;
    int wi = tid >> 5, lane = tid & 31;
    int n = (blockIdx.x << 3) + wi;
    if (n >= NNODES) return;
    int r0 = g_rowptr[n], r1 = g_rowptr[n + 1];

    const float4* ES4 = (const float4*)g_es;
    float4 edq = ((const float4*)g_ed)[n];
    int hl = lane >> 3;   // head owning channels 4*lane..4*lane+3

    float a0 = 0.f, a1 = 0.f, a2 = 0.f, a3 = 0.f, wsum = 0.f;
    const uint2* HH2 = (const uint2*)g_hh;

    for (int base = r0; base < r1; base += 32) {
        int cnt = min(32, r1 - base);
        __syncwarp();
        if (lane < cnt) {
            int s = g_csr[base + lane];
            ss[wi][lane] = s;
            float4 esq = ES4[s];
            float e0 = esq.x + edq.x; e0 = e0 > 0.f ? e0 : SLOPE * e0;
            float e1 = esq.y + edq.y; e1 = e1 > 0.f ? e1 : SLOPE * e1;
            float e2 = esq.z + edq.z; e2 = e2 > 0.f ? e2 : SLOPE * e2;
            float e3 = esq.w + edq.w; e3 = e3 > 0.f ? e3 : SLOPE * e3;
            sw[wi][lane] = make_float4(__expf(e0), __expf(e1), __expf(e2), __expf(e3));
        }
        __syncwarp();
        const float* swf = (const float*)&sw[wi][0];
#pragma unroll 4
        for (int j = 0; j < cnt; j++) {
            int s = ss[wi][j];                 // LDS broadcast
            float wj = swf[j * 4 + hl];        // LDS, 4 banks broadcast
            wsum += wj;
            uint2 hv = HH2[s * 32 + lane];     // 8B gather (L2)
            float2 f0 = __half22float2(*(const __half2*)&hv.x);
            float2 f1 = __half22float2(*(const __half2*)&hv.y);
            a0 += wj * f0.x; a1 += wj * f0.y;
            a2 += wj * f1.x; a3 += wj * f1.y;
        }
    }

    float inv = 1.f / (wsum + 1e-16f);
    int c0 = lane * 4;
    float v0 = a0 * inv + bias[c0 + 0];
    float v1 = a1 * inv + bias[c0 + 1];
    float v2 = a2 * inv + bias[c0 + 2];
    float v3 = a3 * inv + bias[c0 + 3];
    if (do_elu) {
        v0 = v0 > 0.f ? v0 : expm1f(v0);
        v1 = v1 > 0.f ? v1 : expm1f(v1);
        v2 = v2 > 0.f ? v2 : expm1f(v2);
        v3 = v3 > 0.f ? v3 : expm1f(v3);
    }
    ((float4*)g_x)[n * 32 + lane] = make_float4(v0, v1, v2, v3);
}

// ---------------- Layer 2 GEMM (128 -> 40) + logit epilogue ----------------
__global__ void gemm2_kernel(const float* __restrict__ W,
                             const float* __restrict__ avs,
                             const float* __restrict__ avd) {
    __shared__ float Ws[FEAT * OUTC];
    int tid = threadIdx.x;
    for (int i = tid; i < FEAT * OUTC; i += blockDim.x) Ws[i] = W[i];
    __syncthreads();

    int warp = tid >> 5, lane = tid & 31;
    int n = blockIdx.x * 8 + warp;
    if (n >= NNODES) return;

    float xr[4];
#pragma unroll
    for (int j = 0; j < 4; j++) xr[j] = g_x[n * FEAT + j * 32 + lane];

    float acc0 = 0.f, acc1 = 0.f;
#pragma unroll
    for (int k = 0; k < FEAT; k++) {
        float xv = __shfl_sync(0xffffffffu, xr[k >> 5], k & 31);
        acc0 += xv * Ws[k * OUTC + lane];
        if (lane < 8) acc1 += xv * Ws[k * OUTC + 32 + lane];
    }

    g_h2[n * OUTC + lane] = acc0;
    if (lane < 8) g_h2[n * OUTC + 32 + lane] = acc1;

    float pes = acc0 * avs[lane] + ((lane < 8) ? acc1 * avs[32 + lane] : 0.f);
    float ped = acc0 * avd[lane] + ((lane < 8) ? acc1 * avd[32 + lane] : 0.f);
#pragma unroll
    for (int off = 16; off; off >>= 1) {
        pes += __shfl_xor_sync(0xffffffffu, pes, off);
        ped += __shfl_xor_sync(0xffffffffu, ped, off);
    }
    if (lane == 0) { g_es2[n] = pes; g_ed2[n] = ped; }
}

// ---------------- Layer 2 aggregation + log_softmax ----------------
__global__ void agg2_kernel(const float* __restrict__ bias, float* __restrict__ out) {
    __shared__ float sww[8][32];
    __shared__ int   ss[8][32];
    int tid = threadIdx.x;
    int wi = tid >> 5, lane = tid & 31;
    int n = (blockIdx.x << 3) + wi;
    if (n >= NNODES) return;
    int r0 = g_rowptr[n], r1 = g_rowptr[n + 1];
    float edn = g_ed2[n];

    float acc0 = 0.f, acc1 = 0.f, wsum = 0.f;
    for (int base = r0; base < r1; base += 32) {
        int cnt = min(32, r1 - base);
        __syncwarp();
        if (lane < cnt) {
            int s = g_csr[base + lane];
            ss[wi][lane] = s;
            float e = g_es2[s] + edn;
            e = e > 0.f ? e : SLOPE * e;
            sww[wi][lane] = __expf(e);
        }
        __syncwarp();
#pragma unroll 4
        for (int j = 0; j < cnt; j++) {
            int s = ss[wi][j];
            float wj = sww[wi][j];
            wsum += wj;
            acc0 += wj * g_h2[s * OUTC + lane];
            if (lane < 8) acc1 += wj * g_h2[s * OUTC + 32 + lane];
        }
    }

    float inv = 1.f / (wsum + 1e-16f);
    float v0 = acc0 * inv + bias[lane];
    float v1 = (lane < 8) ? (acc1 * inv + bias[32 + lane]) : -1e30f;

    float mx = fmaxf(v0, v1);
#pragma unroll
    for (int off = 16; off; off >>= 1)
        mx = fmaxf(mx, __shfl_xor_sync(0xffffffffu, mx, off));

    float se = expf(v0 - mx) + ((lane < 8) ? expf(v1 - mx) : 0.f);
#pragma unroll
    for (int off = 16; off; off >>= 1)
        se += __shfl_xor_sync(0xffffffffu, se, off);

    float lse = mx + logf(se);
    out[n * OUTC + lane] = v0 - lse;
    if (lane < 8) out[n * OUTC + 32 + lane] = v1 - lse;
}

// ---------------- launch ----------------
extern "C" void kernel_launch(void* const* d_in, const int* in_sizes, int n_in,
                              void* d_out, int out_size) {
    const float* x   = (const float*)d_in[0];
    const int*   ei  = (const int*)d_in[1];
    const float* W0  = (const float*)d_in[2];
    const float* as0 = (const float*)d_in[3];
    const float* ad0 = (const float*)d_in[4];
    const float* b0  = (const float*)d_in[5];
    const float* W1  = (const float*)d_in[6];
    const float* as1 = (const float*)d_in[7];
    const float* ad1 = (const float*)d_in[8];
    const float* b1  = (const float*)d_in[9];
    const float* W2  = (const float*)d_in[10];
    const float* as2 = (const float*)d_in[11];
    const float* ad2 = (const float*)d_in[12];
    const float* b2  = (const float*)d_in[13];
    float* out = (float*)d_out;

    int E = in_sizes[1] / 2;
    if (E + NNODES > MAXE) return;

    const int GSM = (FEAT * FEAT + 64 * FEAT) * 4;  // 96 KB dynamic smem
    cudaFuncSetAttribute(gemm128_kernel, cudaFuncAttributeMaxDynamicSharedMemorySize, GSM);

    // CSR build (2-level parallel scan)
    zero_cnt_kernel<<<(NNODES + 255) / 256, 256>>>();
    count_kernel<<<(E + 255) / 256, 256>>>(ei, E);
    blocksum_kernel<<<NB, 256>>>();
    scanpart_kernel<<<1, 256>>>();
    rowptr_kernel<<<NB, 256>>>();
    scatter_kernel<<<(E + 255) / 256, 256>>>(ei, E);

    int gemm_grid = (NNODES + 63) / 64;
    int agg_grid  = (NNODES + 7) / 8;

    // layer 0
    gemm128_kernel<<<gemm_grid, 256, GSM>>>(x, 0, W0, as0, ad0);
    agg_kernel<<<agg_grid, 256>>>(b0, 1);
    // layer 1
    gemm128_kernel<<<gemm_grid, 256, GSM>>>(nullptr, 1, W1, as1, ad1);
    agg_kernel<<<agg_grid, 256>>>(b1, 1);
    // layer 2
    gemm2_kernel<<<agg_grid, 256>>>(W2, as2, ad2);
    agg2_kernel<<<agg_grid, 256>>>(b2, out);
}

// round 5
// speedup vs baseline: 1.4743x; 1.0844x over previous
#include <cuda_runtime.h>
#include <cuda_fp16.h>
#include <math.h>

#define NNODES 50000
#define FEAT 128
#define HEADS 4
#define HIDC 32
#define OUTC 40
#define SLOPE 0.2f
#define MAXE 1100000
#define NB 196            // ceil(NNODES/256)

// ---------------- scratch (device globals; no allocation allowed) ----------------
__device__ __align__(16) int   g_cnt[NNODES];
__device__ __align__(16) int   g_rowptr[NNODES + 1];
__device__ __align__(16) int   g_cur[NNODES];
__device__ __align__(16) int   g_csr[MAXE];
__device__ __align__(16) int   g_part[NB];
__device__ __align__(16) unsigned int g_hh[NNODES * 64];   // fp16 messages: 128 half per node
__device__ __align__(16) float g_x[NNODES * FEAT];         // layer-0 output (layer-1 input)
__device__ __align__(16) float g_es[NNODES * HEADS];
__device__ __align__(16) float g_ed[NNODES * HEADS];
__device__ __align__(16) float g_h2[NNODES * OUTC];
__device__ __align__(16) float g_es2[NNODES];
__device__ __align__(16) float g_ed2[NNODES];

// ---------------- f32x2 packed math helpers ----------------
__device__ __forceinline__ void ffma2(unsigned long long& d, unsigned long long a,
                                      unsigned long long b) {
    asm volatile("fma.rn.f32x2 %0, %1, %2, %0;" : "+l"(d) : "l"(a), "l"(b));
}
__device__ __forceinline__ unsigned long long pack2(float x) {
    unsigned long long r;
    asm("mov.b64 %0, {%1, %1};" : "=l"(r) : "f"(x));
    return r;
}
__device__ __forceinline__ float2 unpack2(unsigned long long v) {
    float2 r;
    asm("mov.b64 {%0, %1}, %2;" : "=f"(r.x), "=f"(r.y) : "l"(v));
    return r;
}

// ---------------- CSR build ----------------
__global__ void zero_cnt_kernel() {
    int i = blockIdx.x * blockDim.x + threadIdx.x;
    if (i < NNODES) g_cnt[i] = 0;
}

__global__ void count_kernel(const int* __restrict__ ei, int E) {
    int e = blockIdx.x * blockDim.x + threadIdx.x;
    if (e < E) atomicAdd(&g_cnt[ei[E + e]], 1);
}

__global__ void blocksum_kernel() {
    int b = blockIdx.x, tid = threadIdx.x, lane = tid & 31, w = tid >> 5;
    int i = b * 256 + tid;
    int v = (i < NNODES) ? (g_cnt[i] + 1) : 0;
#pragma unroll
    for (int off = 16; off; off >>= 1) v += __shfl_xor_sync(0xffffffffu, v, off);
    __shared__ int ws[8];
    if (lane == 0) ws[w] = v;
    __syncthreads();
    if (tid == 0) {
        int s = 0;
#pragma unroll
        for (int k = 0; k < 8; k++) s += ws[k];
        g_part[b] = s;
    }
}

__global__ void scanpart_kernel() {
    int tid = threadIdx.x, lane = tid & 31, w = tid >> 5;
    int v = (tid < NB) ? g_part[tid] : 0;
    int orig = v;
#pragma unroll
    for (int off = 1; off < 32; off <<= 1) {
        int t = __shfl_up_sync(0xffffffffu, v, off);
        if (lane >= off) v += t;
    }
    __shared__ int ws[8];
    if (lane == 31) ws[w] = v;
    __syncthreads();
    if (tid == 0) {
        int run = 0;
#pragma unroll
        for (int k = 0; k < 8; k++) { int t = ws[k]; ws[k] = run; run += t; }
        g_rowptr[NNODES] = run;
    }
    __syncthreads();
    int incl = v + ws[w];
    if (tid < NB) g_part[tid] = incl - orig;
}

__global__ void rowptr_kernel() {
    int b = blockIdx.x, tid = threadIdx.x, lane = tid & 31, w = tid >> 5;
    int i = b * 256 + tid;
    int v = (i < NNODES) ? (g_cnt[i] + 1) : 0;
    int orig = v;
#pragma unroll
    for (int off = 1; off < 32; off <<= 1) {
        int t = __shfl_up_sync(0xffffffffu, v, off);
        if (lane >= off) v += t;
    }
    __shared__ int ws[8];
    if (lane == 31) ws[w] = v;
    __syncthreads();
    if (tid == 0) {
        int run = 0;
#pragma unroll
        for (int k = 0; k < 8; k++) { int t = ws[k]; ws[k] = run; run += t; }
    }
    __syncthreads();
    int excl = v - orig + ws[w] + g_part[b];
    if (i < NNODES) {
        g_rowptr[i] = excl;
        g_csr[excl] = i;     // self loop first in row
        g_cur[i]    = excl + 1;
    }
}

__global__ void scatter_kernel(const int* __restrict__ ei, int E) {
    int e = blockIdx.x * blockDim.x + threadIdx.x;
    if (e < E) {
        int s = ei[e];
        int d = ei[E + e];
        int p = atomicAdd(&g_cur[d], 1);
        g_csr[p] = s;
    }
}

// ---------------- GEMM 128x128 (f32x2 packed) + fp16 store + logit epilogue --------
__global__ void gemm128_kernel(const float* __restrict__ xparam, int use_internal,
                               const float* __restrict__ W,
                               const float* __restrict__ avs,
                               const float* __restrict__ avd) {
    extern __shared__ float sm[];
    float* Ws = sm;                    // 128*128 floats
    float* Xs = sm + FEAT * FEAT;      // 64*128 floats
    const float* xin = use_internal ? g_x : xparam;

    int tid = threadIdx.x;
    int node0 = blockIdx.x * 64;

    float4* Ws4 = (float4*)Ws;
    const float4* W4 = (const float4*)W;
#pragma unroll
    for (int i = 0; i < 16; i++) Ws4[tid + i * 256] = W4[tid + i * 256];

    float4* Xs4 = (float4*)Xs;
    const float4* X4 = (const float4*)xin;
#pragma unroll
    for (int i = 0; i < 8; i++) {
        int idx = tid + i * 256;
        int row = idx >> 5, c4 = idx & 31;
        int node = node0 + row;
        float4 v = make_float4(0.f, 0.f, 0.f, 0.f);
        if (node < NNODES) v = X4[node * 32 + c4];
        Xs4[idx] = v;
    }
    __syncthreads();

    int cg = tid & 31;
    int ng = tid >> 5;
    unsigned long long acc[8][2];
#pragma unroll
    for (int i = 0; i < 8; i++) { acc[i][0] = 0ull; acc[i][1] = 0ull; }

    const float* xbase = Xs + (ng * 8) * FEAT;
    const ulonglong2* Ws2 = (const ulonglong2*)Ws;
#pragma unroll 4
    for (int k = 0; k < FEAT; k++) {
        ulonglong2 w = Ws2[k * 32 + cg];
#pragma unroll
        for (int i = 0; i < 8; i++) {
            unsigned long long xx = pack2(xbase[i * FEAT + k]);
            ffma2(acc[i][0], xx, w.x);
            ffma2(acc[i][1], xx, w.y);
        }
    }

    int head = cg >> 3, sub = cg & 7;
    float as0 = avs[head * HIDC + sub * 4 + 0], as1 = avs[head * HIDC + sub * 4 + 1];
    float as2 = avs[head * HIDC + sub * 4 + 2], as3 = avs[head * HIDC + sub * 4 + 3];
    float ad0 = avd[head * HIDC + sub * 4 + 0], ad1 = avd[head * HIDC + sub * 4 + 1];
    float ad2 = avd[head * HIDC + sub * 4 + 2], ad3 = avd[head * HIDC + sub * 4 + 3];

    uint2* HH2 = (uint2*)g_hh;
#pragma unroll
    for (int i = 0; i < 8; i++) {
        int node = node0 + ng * 8 + i;
        float2 p0 = unpack2(acc[i][0]);
        float2 p1 = unpack2(acc[i][1]);
        float pes = p0.x * as0 + p0.y * as1 + p1.x * as2 + p1.y * as3;
        float ped = p0.x * ad0 + p0.y * ad1 + p1.x * ad2 + p1.y * ad3;
#pragma unroll
        for (int off = 1; off < 8; off <<= 1) {
            pes += __shfl_xor_sync(0xffffffffu, pes, off);
            ped += __shfl_xor_sync(0xffffffffu, ped, off);
        }
        if (node < NNODES) {
            __half2 hlo = __floats2half2_rn(p0.x, p0.y);
            __half2 hhi = __floats2half2_rn(p1.x, p1.y);
            uint2 hv;
            hv.x = *(unsigned int*)&hlo;
            hv.y = *(unsigned int*)&hhi;
            HH2[node * 32 + cg] = hv;
            if (sub == 0) {
                g_es[node * HEADS + head] = pes;
                g_ed[node * HEADS + head] = ped;
            }
        }
    }
}

// ---------------- Aggregation, layer 0: warp per dst node ----------------
__global__ void agg_kernel(const float* __restrict__ bias) {
    __shared__ float4 sw[8][32];
    __shared__ int    ss[8][32];
    int tid = threadIdx.x;
    int wi = tid >> 5, lane = tid & 31;
    int n = (blockIdx.x << 3) + wi;
    if (n >= NNODES) return;
    int r0 = g_rowptr[n], r1 = g_rowptr[n + 1];

    const float4* ES4 = (const float4*)g_es;
    float4 edq = ((const float4*)g_ed)[n];
    int hl = lane >> 3;

    float a0 = 0.f, a1 = 0.f, a2 = 0.f, a3 = 0.f, wsum = 0.f;
    const uint2* HH2 = (const uint2*)g_hh;

    for (int base = r0; base < r1; base += 32) {
        int cnt = min(32, r1 - base);
        __syncwarp();
        if (lane < cnt) {
            int s = g_csr[base + lane];
            ss[wi][lane] = s;
            float4 esq = ES4[s];
            float e0 = esq.x + edq.x; e0 = e0 > 0.f ? e0 : SLOPE * e0;
            float e1 = esq.y + edq.y; e1 = e1 > 0.f ? e1 : SLOPE * e1;
            float e2 = esq.z + edq.z; e2 = e2 > 0.f ? e2 : SLOPE * e2;
            float e3 = esq.w + edq.w; e3 = e3 > 0.f ? e3 : SLOPE * e3;
            sw[wi][lane] = make_float4(__expf(e0), __expf(e1), __expf(e2), __expf(e3));
        }
        __syncwarp();
        const float* swf = (const float*)&sw[wi][0];
#pragma unroll 4
        for (int j = 0; j < cnt; j++) {
            int s = ss[wi][j];
            float wj = swf[j * 4 + hl];
            wsum += wj;
            uint2 hv = HH2[s * 32 + lane];
            float2 f0 = __half22float2(*(const __half2*)&hv.x);
            float2 f1 = __half22float2(*(const __half2*)&hv.y);
            a0 += wj * f0.x; a1 += wj * f0.y;
            a2 += wj * f1.x; a3 += wj * f1.y;
        }
    }

    float inv = 1.f / (wsum + 1e-16f);
    int c0 = lane * 4;
    float v0 = a0 * inv + bias[c0 + 0];
    float v1 = a1 * inv + bias[c0 + 1];
    float v2 = a2 * inv + bias[c0 + 2];
    float v3 = a3 * inv + bias[c0 + 3];
    v0 = v0 > 0.f ? v0 : expm1f(v0);
    v1 = v1 > 0.f ? v1 : expm1f(v1);
    v2 = v2 > 0.f ? v2 : expm1f(v2);
    v3 = v3 > 0.f ? v3 : expm1f(v3);
    ((float4*)g_x)[n * 32 + lane] = make_float4(v0, v1, v2, v3);
}

// ---------------- Layer-1 aggregation FUSED with layer-2 GEMM ----------------
// 1024-thread blocks (32 warps = 32 nodes). Dynamic smem (56 KB):
//   [0]                 Ws   : FEAT*OUTC floats (20 KB)   - W2 tile
//   [FEAT*OUTC]         xst  : 32*FEAT floats   (16 KB)   - staged x per warp
//   [+32*FEAT]          sw   : 32*32 float4     (16 KB)   - edge weights
//   [+32*32*4]          ss   : 32*32 int        ( 4 KB)   - edge sources
#define AGG1F_SMEM ((FEAT * OUTC + 32 * FEAT + 32 * 32 * 4 + 32 * 32) * 4)

__global__ __launch_bounds__(1024, 2) void agg1f_kernel(
    const float* __restrict__ bias,    // b1
    const float* __restrict__ W2,
    const float* __restrict__ avs2,
    const float* __restrict__ avd2
) {
    extern __shared__ float smf[];
    float*  Ws  = smf;                                   // 20 KB
    float*  xst = smf + FEAT * OUTC;                     // 16 KB
    float4* sw  = (float4*)(xst + 32 * FEAT);            // 16 KB
    int*    ss  = (int*)(sw + 32 * 32);                  //  4 KB

    int tid = threadIdx.x;
    int wi = tid >> 5, lane = tid & 31;

    for (int i = tid; i < FEAT * OUTC; i += 1024) Ws[i] = W2[i];
    __syncthreads();

    int n = (blockIdx.x << 5) + wi;
    bool valid = (n < NNODES);
    int r0 = 0, r1 = 0;
    if (valid) { r0 = g_rowptr[n]; r1 = g_rowptr[n + 1]; }

    const float4* ES4 = (const float4*)g_es;
    float4 edq = valid ? ((const float4*)g_ed)[n] : make_float4(0.f, 0.f, 0.f, 0.f);
    int hl = lane >> 3;

    float a0 = 0.f, a1 = 0.f, a2 = 0.f, a3 = 0.f, wsum = 0.f;
    const uint2* HH2 = (const uint2*)g_hh;
    float4* swr = sw + wi * 32;
    int*    ssr = ss + wi * 32;

    for (int base = r0; base < r1; base += 32) {
        int cnt = min(32, r1 - base);
        __syncwarp();
        if (lane < cnt) {
            int s = g_csr[base + lane];
            ssr[lane] = s;
            float4 esq = ES4[s];
            float e0 = esq.x + edq.x; e0 = e0 > 0.f ? e0 : SLOPE * e0;
            float e1 = esq.y + edq.y; e1 = e1 > 0.f ? e1 : SLOPE * e1;
            float e2 = esq.z + edq.z; e2 = e2 > 0.f ? e2 : SLOPE * e2;
            float e3 = esq.w + edq.w; e3 = e3 > 0.f ? e3 : SLOPE * e3;
            swr[lane] = make_float4(__expf(e0), __expf(e1), __expf(e2), __expf(e3));
        }
        __syncwarp();
        const float* swf = (const float*)swr;
#pragma unroll 4
        for (int j = 0; j < cnt; j++) {
            int s = ssr[j];
            float wj = swf[j * 4 + hl];
            wsum += wj;
            uint2 hv = HH2[s * 32 + lane];
            float2 f0 = __half22float2(*(const __half2*)&hv.x);
            float2 f1 = __half22float2(*(const __half2*)&hv.y);
            a0 += wj * f0.x; a1 += wj * f0.y;
            a2 += wj * f1.x; a3 += wj * f1.y;
        }
    }

    float inv = 1.f / (wsum + 1e-16f);
    int c0 = lane * 4;
    float v0 = a0 * inv + bias[c0 + 0];
    float v1 = a1 * inv + bias[c0 + 1];
    float v2 = a2 * inv + bias[c0 + 2];
    float v3 = a3 * inv + bias[c0 + 3];
    v0 = v0 > 0.f ? v0 : expm1f(v0);
    v1 = v1 > 0.f ? v1 : expm1f(v1);
    v2 = v2 > 0.f ? v2 : expm1f(v2);
    v3 = v3 > 0.f ? v3 : expm1f(v3);

    // stage x[n] (128 floats across warp) for the 128x40 product
    float* xw = xst + wi * FEAT;
    xw[c0 + 0] = v0;
    xw[c0 + 1] = v1;
    xw[c0 + 2] = v2;
    xw[c0 + 3] = v3;
    __syncwarp();

    float acc0 = 0.f, acc1 = 0.f;
    const float4* xq = (const float4*)xw;
#pragma unroll 8
    for (int k4 = 0; k4 < FEAT / 4; k4++) {
        float4 xv = xq[k4];                    // LDS.128 broadcast
        int k = k4 * 4;
        acc0 += xv.x * Ws[(k + 0) * OUTC + lane];
        acc0 += xv.y * Ws[(k + 1) * OUTC + lane];
        acc0 += xv.z * Ws[(k + 2) * OUTC + lane];
        acc0 += xv.w * Ws[(k + 3) * OUTC + lane];
        if (lane < 8) {
            acc1 += xv.x * Ws[(k + 0) * OUTC + 32 + lane];
            acc1 += xv.y * Ws[(k + 1) * OUTC + 32 + lane];
            acc1 += xv.z * Ws[(k + 2) * OUTC + 32 + lane];
            acc1 += xv.w * Ws[(k + 3) * OUTC + 32 + lane];
        }
    }

    float pes = acc0 * avs2[lane] + ((lane < 8) ? acc1 * avs2[32 + lane] : 0.f);
    float ped = acc0 * avd2[lane] + ((lane < 8) ? acc1 * avd2[32 + lane] : 0.f);
#pragma unroll
    for (int off = 16; off; off >>= 1) {
        pes += __shfl_xor_sync(0xffffffffu, pes, off);
        ped += __shfl_xor_sync(0xffffffffu, ped, off);
    }

    if (valid) {
        g_h2[n * OUTC + lane] = acc0;
        if (lane < 8) g_h2[n * OUTC + 32 + lane] = acc1;
        if (lane == 0) { g_es2[n] = pes; g_ed2[n] = ped; }
    }
}

// ---------------- Layer 2 aggregation + log_softmax ----------------
__global__ void agg2_kernel(const float* __restrict__ bias, float* __restrict__ out) {
    __shared__ float sww[8][32];
    __shared__ int   ss[8][32];
    int tid = threadIdx.x;
    int wi = tid >> 5, lane = tid & 31;
    int n = (blockIdx.x << 3) + wi;
    if (n >= NNODES) return;
    int r0 = g_rowptr[n], r1 = g_rowptr[n + 1];
    float edn = g_ed2[n];

    float acc0 = 0.f, acc1 = 0.f, wsum = 0.f;
    for (int base = r0; base < r1; base += 32) {
        int cnt = min(32, r1 - base);
        __syncwarp();
        if (lane < cnt) {
            int s = g_csr[base + lane];
            ss[wi][lane] = s;
            float e = g_es2[s] + edn;
            e = e > 0.f ? e : SLOPE * e;
            sww[wi][lane] = __expf(e);
        }
        __syncwarp();
#pragma unroll 4
        for (int j = 0; j < cnt; j++) {
            int s = ss[wi][j];
            float wj = sww[wi][j];
            wsum += wj;
            acc0 += wj * g_h2[s * OUTC + lane];
            if (lane < 8) acc1 += wj * g_h2[s * OUTC + 32 + lane];
        }
    }

    float inv = 1.f / (wsum + 1e-16f);
    float v0 = acc0 * inv + bias[lane];
    float v1 = (lane < 8) ? (acc1 * inv + bias[32 + lane]) : -1e30f;

    float mx = fmaxf(v0, v1);
#pragma unroll
    for (int off = 16; off; off >>= 1)
        mx = fmaxf(mx, __shfl_xor_sync(0xffffffffu, mx, off));

    float se = expf(v0 - mx) + ((lane < 8) ? expf(v1 - mx) : 0.f);
#pragma unroll
    for (int off = 16; off; off >>= 1)
        se += __shfl_xor_sync(0xffffffffu, se, off);

    float lse = mx + logf(se);
    out[n * OUTC + lane] = v0 - lse;
    if (lane < 8) out[n * OUTC + 32 + lane] = v1 - lse;
}

// ---------------- launch ----------------
extern "C" void kernel_launch(void* const* d_in, const int* in_sizes, int n_in,
                              void* d_out, int out_size) {
    const float* x   = (const float*)d_in[0];
    const int*   ei  = (const int*)d_in[1];
    const float* W0  = (const float*)d_in[2];
    const float* as0 = (const float*)d_in[3];
    const float* ad0 = (const float*)d_in[4];
    const float* b0  = (const float*)d_in[5];
    const float* W1  = (const float*)d_in[6];
    const float* as1 = (const float*)d_in[7];
    const float* ad1 = (const float*)d_in[8];
    const float* b1  = (const float*)d_in[9];
    const float* W2  = (const float*)d_in[10];
    const float* as2 = (const float*)d_in[11];
    const float* ad2 = (const float*)d_in[12];
    const float* b2  = (const float*)d_in[13];
    float* out = (float*)d_out;

    int E = in_sizes[1] / 2;
    if (E + NNODES > MAXE) return;

    const int GSM = (FEAT * FEAT + 64 * FEAT) * 4;  // 96 KB dynamic smem
    cudaFuncSetAttribute(gemm128_kernel, cudaFuncAttributeMaxDynamicSharedMemorySize, GSM);
    cudaFuncSetAttribute(agg1f_kernel, cudaFuncAttributeMaxDynamicSharedMemorySize, AGG1F_SMEM);

    // CSR build (2-level parallel scan)
    zero_cnt_kernel<<<(NNODES + 255) / 256, 256>>>();
    count_kernel<<<(E + 255) / 256, 256>>>(ei, E);
    blocksum_kernel<<<NB, 256>>>();
    scanpart_kernel<<<1, 256>>>();
    rowptr_kernel<<<NB, 256>>>();
    scatter_kernel<<<(E + 255) / 256, 256>>>(ei, E);

    int gemm_grid = (NNODES + 63) / 64;
    int agg_grid  = (NNODES + 7) / 8;
    int agg1f_grid = (NNODES + 31) / 32;

    // layer 0
    gemm128_kernel<<<gemm_grid, 256, GSM>>>(x, 0, W0, as0, ad0);
    agg_kernel<<<agg_grid, 256>>>(b0);
    // layer 1 (+ fused layer-2 GEMM)
    gemm128_kernel<<<gemm_grid, 256, GSM>>>(nullptr, 1, W1, as1, ad1);
    agg1f_kernel<<<agg1f_grid, 1024, AGG1F_SMEM>>>(b1, W2, as2, ad2);
    // layer 2 aggregation + log_softmax
    agg2_kernel<<<agg_grid, 256>>>(b2, out);
}

// round 6
// speedup vs baseline: 1.5291x; 1.0372x over previous
#include <cuda_runtime.h>
#include <cuda_fp16.h>
#include <math.h>

#define NNODES 50000
#define FEAT 128
#define HEADS 4
#define HIDC 32
#define OUTC 40
#define SLOPE 0.2f
#define MAXE 1100000
#define NB 196            // ceil(NNODES/256)

// ---------------- scratch (device globals; no allocation allowed) ----------------
__device__ __align__(16) int   g_cnt[NNODES];
__device__ __align__(16) int   g_rowptr[NNODES + 1];
__device__ __align__(16) int   g_cur[NNODES];
__device__ __align__(16) int   g_csr[MAXE];
__device__ __align__(16) int   g_part[NB];
__device__ __align__(16) unsigned int g_hh[NNODES * 64];   // fp16 messages: 128 half per node
__device__ __align__(16) float g_x[NNODES * FEAT];         // layer-0 output (layer-1 input)
__device__ __align__(16) float g_es[NNODES * HEADS];
__device__ __align__(16) float g_ed[NNODES * HEADS];
__device__ __align__(16) float g_h2[NNODES * OUTC];
__device__ __align__(16) float g_es2[NNODES];
__device__ __align__(16) float g_ed2[NNODES];

// ---------------- f32x2 packed math helpers ----------------
__device__ __forceinline__ void ffma2(unsigned long long& d, unsigned long long a,
                                      unsigned long long b) {
    asm volatile("fma.rn.f32x2 %0, %1, %2, %0;" : "+l"(d) : "l"(a), "l"(b));
}
__device__ __forceinline__ unsigned long long pack2(float x) {
    unsigned long long r;
    asm("mov.b64 %0, {%1, %1};" : "=l"(r) : "f"(x));
    return r;
}
__device__ __forceinline__ float2 unpack2(unsigned long long v) {
    float2 r;
    asm("mov.b64 {%0, %1}, %2;" : "=f"(r.x), "=f"(r.y) : "l"(v));
    return r;
}

// ---------------- CSR build ----------------
__global__ void zero_cnt_kernel() {
    int i = blockIdx.x * blockDim.x + threadIdx.x;
    if (i < NNODES) g_cnt[i] = 0;
}

__global__ void count_kernel(const int* __restrict__ ei, int E) {
    int e = blockIdx.x * blockDim.x + threadIdx.x;
    if (e < E) atomicAdd(&g_cnt[ei[E + e]], 1);
}

__global__ void blocksum_kernel() {
    int b = blockIdx.x, tid = threadIdx.x, lane = tid & 31, w = tid >> 5;
    int i = b * 256 + tid;
    int v = (i < NNODES) ? (g_cnt[i] + 1) : 0;
#pragma unroll
    for (int off = 16; off; off >>= 1) v += __shfl_xor_sync(0xffffffffu, v, off);
    __shared__ int ws[8];
    if (lane == 0) ws[w] = v;
    __syncthreads();
    if (tid == 0) {
        int s = 0;
#pragma unroll
        for (int k = 0; k < 8; k++) s += ws[k];
        g_part[b] = s;
    }
}

// rowptr + inline exclusive scan of g_part (each block sums its predecessors)
__global__ void rowptr_kernel() {
    int b = blockIdx.x, tid = threadIdx.x, lane = tid & 31, w = tid >> 5;

    // base = sum of g_part[0..b-1], block-cooperative
    __shared__ int sbase;
    int pre = 0;
    for (int i = tid; i < b; i += 256) pre += g_part[i];
#pragma unroll
    for (int off = 16; off; off >>= 1) pre += __shfl_xor_sync(0xffffffffu, pre, off);
    __shared__ int pw[8];
    if (lane == 0) pw[w] = pre;
    __syncthreads();
    if (tid == 0) {
        int s = 0;
#pragma unroll
        for (int k = 0; k < 8; k++) s += pw[k];
        sbase = s;
    }
    __syncthreads();
    int base = sbase;

    int i = b * 256 + tid;
    int v = (i < NNODES) ? (g_cnt[i] + 1) : 0;
    int orig = v;
#pragma unroll
    for (int off = 1; off < 32; off <<= 1) {
        int t = __shfl_up_sync(0xffffffffu, v, off);
        if (lane >= off) v += t;
    }
    __shared__ int ws[8];
    if (lane == 31) ws[w] = v;
    __syncthreads();
    if (tid == 0) {
        int run = 0;
#pragma unroll
        for (int k = 0; k < 8; k++) { int t = ws[k]; ws[k] = run; run += t; }
    }
    __syncthreads();
    int excl = v - orig + ws[w] + base;
    if (i < NNODES) {
        g_rowptr[i] = excl;
        g_csr[excl] = i;     // self loop first in row
        g_cur[i]    = excl + 1;
        if (i == NNODES - 1) g_rowptr[NNODES] = excl + orig;
    }
}

__global__ void scatter_kernel(const int* __restrict__ ei, int E) {
    int e = blockIdx.x * blockDim.x + threadIdx.x;
    if (e < E) {
        int s = ei[e];
        int d = ei[E + e];
        int p = atomicAdd(&g_cur[d], 1);
        g_csr[p] = s;
    }
}

// ---------------- GEMM 128x128 (f32x2 packed) + fp16 store + logit epilogue --------
__global__ void gemm128_kernel(const float* __restrict__ xparam, int use_internal,
                               const float* __restrict__ W,
                               const float* __restrict__ avs,
                               const float* __restrict__ avd) {
    extern __shared__ float sm[];
    float* Ws = sm;                    // 128*128 floats
    float* Xs = sm + FEAT * FEAT;      // 64*128 floats
    const float* xin = use_internal ? g_x : xparam;

    int tid = threadIdx.x;
    int node0 = blockIdx.x * 64;

    float4* Ws4 = (float4*)Ws;
    const float4* W4 = (const float4*)W;
#pragma unroll
    for (int i = 0; i < 16; i++) Ws4[tid + i * 256] = W4[tid + i * 256];

    float4* Xs4 = (float4*)Xs;
    const float4* X4 = (const float4*)xin;
#pragma unroll
    for (int i = 0; i < 8; i++) {
        int idx = tid + i * 256;
        int row = idx >> 5, c4 = idx & 31;
        int node = node0 + row;
        float4 v = make_float4(0.f, 0.f, 0.f, 0.f);
        if (node < NNODES) v = X4[node * 32 + c4];
        Xs4[idx] = v;
    }
    __syncthreads();

    int cg = tid & 31;
    int ng = tid >> 5;
    unsigned long long acc[8][2];
#pragma unroll
    for (int i = 0; i < 8; i++) { acc[i][0] = 0ull; acc[i][1] = 0ull; }

    const float* xbase = Xs + (ng * 8) * FEAT;
    const ulonglong2* Ws2 = (const ulonglong2*)Ws;
#pragma unroll 4
    for (int k = 0; k < FEAT; k++) {
        ulonglong2 w = Ws2[k * 32 + cg];
#pragma unroll
        for (int i = 0; i < 8; i++) {
            unsigned long long xx = pack2(xbase[i * FEAT + k]);
            ffma2(acc[i][0], xx, w.x);
            ffma2(acc[i][1], xx, w.y);
        }
    }

    int head = cg >> 3, sub = cg & 7;
    float as0 = avs[head * HIDC + sub * 4 + 0], as1 = avs[head * HIDC + sub * 4 + 1];
    float as2 = avs[head * HIDC + sub * 4 + 2], as3 = avs[head * HIDC + sub * 4 + 3];
    float ad0 = avd[head * HIDC + sub * 4 + 0], ad1 = avd[head * HIDC + sub * 4 + 1];
    float ad2 = avd[head * HIDC + sub * 4 + 2], ad3 = avd[head * HIDC + sub * 4 + 3];

    uint2* HH2 = (uint2*)g_hh;
#pragma unroll
    for (int i = 0; i < 8; i++) {
        int node = node0 + ng * 8 + i;
        float2 p0 = unpack2(acc[i][0]);
        float2 p1 = unpack2(acc[i][1]);
        float pes = p0.x * as0 + p0.y * as1 + p1.x * as2 + p1.y * as3;
        float ped = p0.x * ad0 + p0.y * ad1 + p1.x * ad2 + p1.y * ad3;
#pragma unroll
        for (int off = 1; off < 8; off <<= 1) {
            pes += __shfl_xor_sync(0xffffffffu, pes, off);
            ped += __shfl_xor_sync(0xffffffffu, ped, off);
        }
        if (node < NNODES) {
            __half2 hlo = __floats2half2_rn(p0.x, p0.y);
            __half2 hhi = __floats2half2_rn(p1.x, p1.y);
            uint2 hv;
            hv.x = *(unsigned int*)&hlo;
            hv.y = *(unsigned int*)&hhi;
            HH2[node * 32 + cg] = hv;
            if (sub == 0) {
                g_es[node * HEADS + head] = pes;
                g_ed[node * HEADS + head] = ped;
            }
        }
    }
}

// ---------------- Aggregation, layer 0: warp per dst node ----------------
__global__ void agg_kernel(const float* __restrict__ bias) {
    __shared__ float4 sw[8][32];
    __shared__ int    ss[8][32];
    int tid = threadIdx.x;
    int wi = tid >> 5, lane = tid & 31;
    int n = (blockIdx.x << 3) + wi;
    if (n >= NNODES) return;
    int r0 = g_rowptr[n], r1 = g_rowptr[n + 1];

    const float4* ES4 = (const float4*)g_es;
    float4 edq = ((const float4*)g_ed)[n];
    int hl = lane >> 3;

    float a0 = 0.f, a1 = 0.f, a2 = 0.f, a3 = 0.f, wsum = 0.f;
    const uint2* HH2 = (const uint2*)g_hh;

    for (int base = r0; base < r1; base += 32) {
        int cnt = min(32, r1 - base);
        __syncwarp();
        if (lane < cnt) {
            int s = g_csr[base + lane];
            ss[wi][lane] = s;
            float4 esq = ES4[s];
            float e0 = esq.x + edq.x; e0 = e0 > 0.f ? e0 : SLOPE * e0;
            float e1 = esq.y + edq.y; e1 = e1 > 0.f ? e1 : SLOPE * e1;
            float e2 = esq.z + edq.z; e2 = e2 > 0.f ? e2 : SLOPE * e2;
            float e3 = esq.w + edq.w; e3 = e3 > 0.f ? e3 : SLOPE * e3;
            sw[wi][lane] = make_float4(__expf(e0), __expf(e1), __expf(e2), __expf(e3));
        }
        __syncwarp();
        const float* swf = (const float*)&sw[wi][0];
#pragma unroll 4
        for (int j = 0; j < cnt; j++) {
            int s = ss[wi][j];
            float wj = swf[j * 4 + hl];
            wsum += wj;
            uint2 hv = HH2[s * 32 + lane];
            float2 f0 = __half22float2(*(const __half2*)&hv.x);
            float2 f1 = __half22float2(*(const __half2*)&hv.y);
            a0 += wj * f0.x; a1 += wj * f0.y;
            a2 += wj * f1.x; a3 += wj * f1.y;
        }
    }

    float inv = 1.f / (wsum + 1e-16f);
    int c0 = lane * 4;
    float v0 = a0 * inv + bias[c0 + 0];
    float v1 = a1 * inv + bias[c0 + 1];
    float v2 = a2 * inv + bias[c0 + 2];
    float v3 = a3 * inv + bias[c0 + 3];
    v0 = v0 > 0.f ? v0 : expm1f(v0);
    v1 = v1 > 0.f ? v1 : expm1f(v1);
    v2 = v2 > 0.f ? v2 : expm1f(v2);
    v3 = v3 > 0.f ? v3 : expm1f(v3);
    ((float4*)g_x)[n * 32 + lane] = make_float4(v0, v1, v2, v3);
}

// ---------------- Layer-1 aggregation FUSED with layer-2 GEMM ----------------
#define AGG1F_SMEM ((FEAT * OUTC + 32 * FEAT + 32 * 32 * 4 + 32 * 32) * 4)

__global__ __launch_bounds__(1024, 2) void agg1f_kernel(
    const float* __restrict__ bias,    // b1
    const float* __restrict__ W2,
    const float* __restrict__ avs2,
    const float* __restrict__ avd2
) {
    extern __shared__ float smf[];
    float*  Ws  = smf;                                   // 20 KB
    float*  xst = smf + FEAT * OUTC;                     // 16 KB
    float4* sw  = (float4*)(xst + 32 * FEAT);            // 16 KB
    int*    ss  = (int*)(sw + 32 * 32);                  //  4 KB

    int tid = threadIdx.x;
    int wi = tid >> 5, lane = tid & 31;

    for (int i = tid; i < FEAT * OUTC; i += 1024) Ws[i] = W2[i];
    __syncthreads();

    int n = (blockIdx.x << 5) + wi;
    bool valid = (n < NNODES);
    int r0 = 0, r1 = 0;
    if (valid) { r0 = g_rowptr[n]; r1 = g_rowptr[n + 1]; }

    const float4* ES4 = (const float4*)g_es;
    float4 edq = valid ? ((const float4*)g_ed)[n] : make_float4(0.f, 0.f, 0.f, 0.f);
    int hl = lane >> 3;

    float a0 = 0.f, a1 = 0.f, a2 = 0.f, a3 = 0.f, wsum = 0.f;
    const uint2* HH2 = (const uint2*)g_hh;
    float4* swr = sw + wi * 32;
    int*    ssr = ss + wi * 32;

    for (int base = r0; base < r1; base += 32) {
        int cnt = min(32, r1 - base);
        __syncwarp();
        if (lane < cnt) {
            int s = g_csr[base + lane];
            ssr[lane] = s;
            float4 esq = ES4[s];
            float e0 = esq.x + edq.x; e0 = e0 > 0.f ? e0 : SLOPE * e0;
            float e1 = esq.y + edq.y; e1 = e1 > 0.f ? e1 : SLOPE * e1;
            float e2 = esq.z + edq.z; e2 = e2 > 0.f ? e2 : SLOPE * e2;
            float e3 = esq.w + edq.w; e3 = e3 > 0.f ? e3 : SLOPE * e3;
            swr[lane] = make_float4(__expf(e0), __expf(e1), __expf(e2), __expf(e3));
        }
        __syncwarp();
        const float* swf = (const float*)swr;
#pragma unroll 4
        for (int j = 0; j < cnt; j++) {
            int s = ssr[j];
            float wj = swf[j * 4 + hl];
            wsum += wj;
            uint2 hv = HH2[s * 32 + lane];
            float2 f0 = __half22float2(*(const __half2*)&hv.x);
            float2 f1 = __half22float2(*(const __half2*)&hv.y);
            a0 += wj * f0.x; a1 += wj * f0.y;
            a2 += wj * f1.x; a3 += wj * f1.y;
        }
    }

    float inv = 1.f / (wsum + 1e-16f);
    int c0 = lane * 4;
    float v0 = a0 * inv + bias[c0 + 0];
    float v1 = a1 * inv + bias[c0 + 1];
    float v2 = a2 * inv + bias[c0 + 2];
    float v3 = a3 * inv + bias[c0 + 3];
    v0 = v0 > 0.f ? v0 : expm1f(v0);
    v1 = v1 > 0.f ? v1 : expm1f(v1);
    v2 = v2 > 0.f ? v2 : expm1f(v2);
    v3 = v3 > 0.f ? v3 : expm1f(v3);

    float* xw = xst + wi * FEAT;
    xw[c0 + 0] = v0;
    xw[c0 + 1] = v1;
    xw[c0 + 2] = v2;
    xw[c0 + 3] = v3;
    __syncwarp();

    float acc0 = 0.f, acc1 = 0.f;
    const float4* xq = (const float4*)xw;
#pragma unroll 8
    for (int k4 = 0; k4 < FEAT / 4; k4++) {
        float4 xv = xq[k4];
        int k = k4 * 4;
        acc0 += xv.x * Ws[(k + 0) * OUTC + lane];
        acc0 += xv.y * Ws[(k + 1) * OUTC + lane];
        acc0 += xv.z * Ws[(k + 2) * OUTC + lane];
        acc0 += xv.w * Ws[(k + 3) * OUTC + lane];
        if (lane < 8) {
            acc1 += xv.x * Ws[(k + 0) * OUTC + 32 + lane];
            acc1 += xv.y * Ws[(k + 1) * OUTC + 32 + lane];
            acc1 += xv.z * Ws[(k + 2) * OUTC + 32 + lane];
            acc1 += xv.w * Ws[(k + 3) * OUTC + 32 + lane];
        }
    }

    float pes = acc0 * avs2[lane] + ((lane < 8) ? acc1 * avs2[32 + lane] : 0.f);
    float ped = acc0 * avd2[lane] + ((lane < 8) ? acc1 * avd2[32 + lane] : 0.f);
#pragma unroll
    for (int off = 16; off; off >>= 1) {
        pes += __shfl_xor_sync(0xffffffffu, pes, off);
        ped += __shfl_xor_sync(0xffffffffu, ped, off);
    }

    if (valid) {
        g_h2[n * OUTC + lane] = acc0;
        if (lane < 8) g_h2[n * OUTC + 32 + lane] = acc1;
        if (lane == 0) { g_es2[n] = pes; g_ed2[n] = ped; }
    }
}

// ---------------- Layer 2 aggregation + log_softmax ----------------
__global__ void agg2_kernel(const float* __restrict__ bias, float* __restrict__ out) {
    __shared__ float sww[8][32];
    __shared__ int   ss[8][32];
    int tid = threadIdx.x;
    int wi = tid >> 5, lane = tid & 31;
    int n = (blockIdx.x << 3) + wi;
    if (n >= NNODES) return;
    int r0 = g_rowptr[n], r1 = g_rowptr[n + 1];
    float edn = g_ed2[n];

    float acc0 = 0.f, acc1 = 0.f, wsum = 0.f;
    for (int base = r0; base < r1; base += 32) {
        int cnt = min(32, r1 - base);
        __syncwarp();
        if (lane < cnt) {
            int s = g_csr[base + lane];
            ss[wi][lane] = s;
            float e = g_es2[s] + edn;
            e = e > 0.f ? e : SLOPE * e;
            sww[wi][lane] = __expf(e);
        }
        __syncwarp();
#pragma unroll 4
        for (int j = 0; j < cnt; j++) {
            int s = ss[wi][j];
            float wj = sww[wi][j];
            wsum += wj;
            acc0 += wj * g_h2[s * OUTC + lane];
            if (lane < 8) acc1 += wj * g_h2[s * OUTC + 32 + lane];
        }
    }

    float inv = 1.f / (wsum + 1e-16f);
    float v0 = acc0 * inv + bias[lane];
    float v1 = (lane < 8) ? (acc1 * inv + bias[32 + lane]) : -1e30f;

    float mx = fmaxf(v0, v1);
#pragma unroll
    for (int off = 16; off; off >>= 1)
        mx = fmaxf(mx, __shfl_xor_sync(0xffffffffu, mx, off));

    float se = expf(v0 - mx) + ((lane < 8) ? expf(v1 - mx) : 0.f);
#pragma unroll
    for (int off = 16; off; off >>= 1)
        se += __shfl_xor_sync(0xffffffffu, se, off);

    float lse = mx + logf(se);
    out[n * OUTC + lane] = v0 - lse;
    if (lane < 8) out[n * OUTC + 32 + lane] = v1 - lse;
}

// ---------------- launch ----------------
extern "C" void kernel_launch(void* const* d_in, const int* in_sizes, int n_in,
                              void* d_out, int out_size) {
    const float* x   = (const float*)d_in[0];
    const int*   ei  = (const int*)d_in[1];
    const float* W0  = (const float*)d_in[2];
    const float* as0 = (const float*)d_in[3];
    const float* ad0 = (const float*)d_in[4];
    const float* b0  = (const float*)d_in[5];
    const float* W1  = (const float*)d_in[6];
    const float* as1 = (const float*)d_in[7];
    const float* ad1 = (const float*)d_in[8];
    const float* b1  = (const float*)d_in[9];
    const float* W2  = (const float*)d_in[10];
    const float* as2 = (const float*)d_in[11];
    const float* ad2 = (const float*)d_in[12];
    const float* b2  = (const float*)d_in[13];
    float* out = (float*)d_out;

    int E = in_sizes[1] / 2;
    if (E + NNODES > MAXE) return;

    const int GSM = (FEAT * FEAT + 64 * FEAT) * 4;  // 96 KB dynamic smem
    cudaFuncSetAttribute(gemm128_kernel, cudaFuncAttributeMaxDynamicSharedMemorySize, GSM);
    cudaFuncSetAttribute(agg1f_kernel, cudaFuncAttributeMaxDynamicSharedMemorySize, AGG1F_SMEM);

    // Second stream for the CSR build (independent of layer-0 GEMM).
    // Created per call: host-side only; replays execute the captured graph,
    // so this never costs timed microseconds. Non-blocking to avoid legacy-
    // stream implicit serialization during capture.
    cudaStream_t s2;
    cudaStreamCreateWithFlags(&s2, cudaStreamNonBlocking);
    cudaEvent_t evFork, evJoin;
    cudaEventCreateWithFlags(&evFork, cudaEventDisableTiming);
    cudaEventCreateWithFlags(&evJoin, cudaEventDisableTiming);

    cudaEventRecord(evFork, 0);
    cudaStreamWaitEvent(s2, evFork, 0);

    // CSR build on s2 (2-level scan folded into rowptr)
    zero_cnt_kernel<<<(NNODES + 255) / 256, 256, 0, s2>>>();
    count_kernel<<<(E + 255) / 256, 256, 0, s2>>>(ei, E);
    blocksum_kernel<<<NB, 256, 0, s2>>>();
    rowptr_kernel<<<NB, 256, 0, s2>>>();
    scatter_kernel<<<(E + 255) / 256, 256, 0, s2>>>(ei, E);
    cudaEventRecord(evJoin, s2);

    int gemm_grid = (NNODES + 63) / 64;
    int agg_grid  = (NNODES + 7) / 8;
    int agg1f_grid = (NNODES + 31) / 32;

    // layer-0 GEMM overlaps the CSR build
    gemm128_kernel<<<gemm_grid, 256, GSM>>>(x, 0, W0, as0, ad0);

    // join: aggregation needs CSR + gemm0
    cudaStreamWaitEvent(0, evJoin, 0);

    agg_kernel<<<agg_grid, 256>>>(b0);
    gemm128_kernel<<<gemm_grid, 256, GSM>>>(nullptr, 1, W1, as1, ad1);
    agg1f_kernel<<<agg1f_grid, 1024, AGG1F_SMEM>>>(b1, W2, as2, ad2);
    agg2_kernel<<<agg_grid, 256>>>(b2, out);
}

// round 7
// speedup vs baseline: 1.5342x; 1.0033x over previous
#include <cuda_runtime.h>
#include <cuda_fp16.h>
#include <math.h>

#define NNODES 50000
#define FEAT 128
#define HEADS 4
#define HIDC 32
#define OUTC 40
#define SLOPE 0.2f
#define MAXE 1100000
#define NB 196            // ceil(NNODES/256)

// ---------------- scratch (device globals; no allocation allowed) ----------------
__device__ __align__(16) int   g_cnt[NNODES];
__device__ __align__(16) int   g_rowptr[NNODES + 1];
__device__ __align__(16) int   g_cur[NNODES];
__device__ __align__(16) int   g_csr[MAXE];
__device__ __align__(16) int   g_part[NB];
__device__ __align__(16) unsigned int g_hh[NNODES * 64];   // fp16 messages: 128 half per node
__device__ __align__(16) float g_x[NNODES * FEAT];         // layer-0 output (layer-1 input)
__device__ __align__(16) float g_es[NNODES * HEADS];
__device__ __align__(16) float g_ed[NNODES * HEADS];
__device__ __align__(16) float g_h2[NNODES * OUTC];
__device__ __align__(16) float g_es2[NNODES];
__device__ __align__(16) float g_ed2[NNODES];

// ---------------- f32x2 packed math helpers ----------------
__device__ __forceinline__ void ffma2(unsigned long long& d, unsigned long long a,
                                      unsigned long long b) {
    asm volatile("fma.rn.f32x2 %0, %1, %2, %0;" : "+l"(d) : "l"(a), "l"(b));
}
__device__ __forceinline__ unsigned long long pack2(float x) {
    unsigned long long r;
    asm("mov.b64 %0, {%1, %1};" : "=l"(r) : "f"(x));
    return r;
}
__device__ __forceinline__ float2 unpack2(unsigned long long v) {
    float2 r;
    asm("mov.b64 {%0, %1}, %2;" : "=f"(r.x), "=f"(r.y) : "l"(v));
    return r;
}

// ---------------- CSR build ----------------
__global__ void zero_cnt_kernel() {
    int i = blockIdx.x * blockDim.x + threadIdx.x;
    if (i < NNODES) g_cnt[i] = 0;
}

__global__ void count_kernel(const int* __restrict__ ei, int E) {
    int e = blockIdx.x * blockDim.x + threadIdx.x;
    if (e < E) atomicAdd(&g_cnt[ei[E + e]], 1);
}

__global__ void blocksum_kernel() {
    int b = blockIdx.x, tid = threadIdx.x, lane = tid & 31, w = tid >> 5;
    int i = b * 256 + tid;
    int v = (i < NNODES) ? (g_cnt[i] + 1) : 0;
#pragma unroll
    for (int off = 16; off; off >>= 1) v += __shfl_xor_sync(0xffffffffu, v, off);
    __shared__ int ws[8];
    if (lane == 0) ws[w] = v;
    __syncthreads();
    if (tid == 0) {
        int s = 0;
#pragma unroll
        for (int k = 0; k < 8; k++) s += ws[k];
        g_part[b] = s;
    }
}

// rowptr + inline exclusive scan of g_part (each block sums its predecessors)
__global__ void rowptr_kernel() {
    int b = blockIdx.x, tid = threadIdx.x, lane = tid & 31, w = tid >> 5;

    // base = sum of g_part[0..b-1], block-cooperative
    __shared__ int sbase;
    int pre = 0;
    for (int i = tid; i < b; i += 256) pre += g_part[i];
#pragma unroll
    for (int off = 16; off; off >>= 1) pre += __shfl_xor_sync(0xffffffffu, pre, off);
    __shared__ int pw[8];
    if (lane == 0) pw[w] = pre;
    __syncthreads();
    if (tid == 0) {
        int s = 0;
#pragma unroll
        for (int k = 0; k < 8; k++) s += pw[k];
        sbase = s;
    }
    __syncthreads();
    int base = sbase;

    int i = b * 256 + tid;
    int v = (i < NNODES) ? (g_cnt[i] + 1) : 0;
    int orig = v;
#pragma unroll
    for (int off = 1; off < 32; off <<= 1) {
        int t = __shfl_up_sync(0xffffffffu, v, off);
        if (lane >= off) v += t;
    }
    __shared__ int ws[8];
    if (lane == 31) ws[w] = v;
    __syncthreads();
    if (tid == 0) {
        int run = 0;
#pragma unroll
        for (int k = 0; k < 8; k++) { int t = ws[k]; ws[k] = run; run += t; }
    }
    __syncthreads();
    int excl = v - orig + ws[w] + base;
    if (i < NNODES) {
        g_rowptr[i] = excl;
        g_csr[excl] = i;     // self loop first in row
        g_cur[i]    = excl + 1;
        if (i == NNODES - 1) g_rowptr[NNODES] = excl + orig;
    }
}

__global__ void scatter_kernel(const int* __restrict__ ei, int E) {
    int e = blockIdx.x * blockDim.x + threadIdx.x;
    if (e < E) {
        int s = ei[e];
        int d = ei[E + e];
        int p = atomicAdd(&g_cur[d], 1);
        g_csr[p] = s;
    }
}

// ---------------- GEMM 128x128 (f32x2 packed) + fp16 store + logit epilogue --------
__global__ void gemm128_kernel(const float* __restrict__ xparam, int use_internal,
                               const float* __restrict__ W,
                               const float* __restrict__ avs,
                               const float* __restrict__ avd) {
    extern __shared__ float sm[];
    float* Ws = sm;                    // 128*128 floats
    float* Xs = sm + FEAT * FEAT;      // 64*128 floats
    const float* xin = use_internal ? g_x : xparam;

    int tid = threadIdx.x;
    int node0 = blockIdx.x * 64;

    float4* Ws4 = (float4*)Ws;
    const float4* W4 = (const float4*)W;
#pragma unroll
    for (int i = 0; i < 16; i++) Ws4[tid + i * 256] = W4[tid + i * 256];

    float4* Xs4 = (float4*)Xs;
    const float4* X4 = (const float4*)xin;
#pragma unroll
    for (int i = 0; i < 8; i++) {
        int idx = tid + i * 256;
        int row = idx >> 5, c4 = idx & 31;
        int node = node0 + row;
        float4 v = make_float4(0.f, 0.f, 0.f, 0.f);
        if (node < NNODES) v = X4[node * 32 + c4];
        Xs4[idx] = v;
    }
    __syncthreads();

    int cg = tid & 31;
    int ng = tid >> 5;
    unsigned long long acc[8][2];
#pragma unroll
    for (int i = 0; i < 8; i++) { acc[i][0] = 0ull; acc[i][1] = 0ull; }

    const float* xbase = Xs + (ng * 8) * FEAT;
    const ulonglong2* Ws2 = (const ulonglong2*)Ws;
#pragma unroll 4
    for (int k = 0; k < FEAT; k++) {
        ulonglong2 w = Ws2[k * 32 + cg];
#pragma unroll
        for (int i = 0; i < 8; i++) {
            unsigned long long xx = pack2(xbase[i * FEAT + k]);
            ffma2(acc[i][0], xx, w.x);
            ffma2(acc[i][1], xx, w.y);
        }
    }

    int head = cg >> 3, sub = cg & 7;
    float as0 = avs[head * HIDC + sub * 4 + 0], as1 = avs[head * HIDC + sub * 4 + 1];
    float as2 = avs[head * HIDC + sub * 4 + 2], as3 = avs[head * HIDC + sub * 4 + 3];
    float ad0 = avd[head * HIDC + sub * 4 + 0], ad1 = avd[head * HIDC + sub * 4 + 1];
    float ad2 = avd[head * HIDC + sub * 4 + 2], ad3 = avd[head * HIDC + sub * 4 + 3];

    uint2* HH2 = (uint2*)g_hh;
#pragma unroll
    for (int i = 0; i < 8; i++) {
        int node = node0 + ng * 8 + i;
        float2 p0 = unpack2(acc[i][0]);
        float2 p1 = unpack2(acc[i][1]);
        float pes = p0.x * as0 + p0.y * as1 + p1.x * as2 + p1.y * as3;
        float ped = p0.x * ad0 + p0.y * ad1 + p1.x * ad2 + p1.y * ad3;
#pragma unroll
        for (int off = 1; off < 8; off <<= 1) {
            pes += __shfl_xor_sync(0xffffffffu, pes, off);
            ped += __shfl_xor_sync(0xffffffffu, ped, off);
        }
        if (node < NNODES) {
            __half2 hlo = __floats2half2_rn(p0.x, p0.y);
            __half2 hhi = __floats2half2_rn(p1.x, p1.y);
            uint2 hv;
            hv.x = *(unsigned int*)&hlo;
            hv.y = *(unsigned int*)&hhi;
            HH2[node * 32 + cg] = hv;
            if (sub == 0) {
                g_es[node * HEADS + head] = pes;
                g_ed[node * HEADS + head] = ped;
            }
        }
    }
}

// ---------------- Aggregation, layer 0: warp per dst node ----------------
__global__ void agg_kernel(const float* __restrict__ bias) {
    __shared__ float4 sw[8][32];
    __shared__ int    ss[8][32];
    int tid = threadIdx.x;
    int wi = tid >> 5, lane = tid & 31;
    int n = (blockIdx.x << 3) + wi;
    if (n >= NNODES) return;
    int r0 = g_rowptr[n], r1 = g_rowptr[n + 1];

    const float4* ES4 = (const float4*)g_es;
    float4 edq = ((const float4*)g_ed)[n];
    int hl = lane >> 3;

    float a0 = 0.f, a1 = 0.f, a2 = 0.f, a3 = 0.f, wsum = 0.f;
    const uint2* HH2 = (const uint2*)g_hh;

    for (int base = r0; base < r1; base += 32) {
        int cnt = min(32, r1 - base);
        __syncwarp();
        if (lane < cnt) {
            int s = g_csr[base + lane];
            ss[wi][lane] = s;
            float4 esq = ES4[s];
            float e0 = esq.x + edq.x; e0 = e0 > 0.f ? e0 : SLOPE * e0;
            float e1 = esq.y + edq.y; e1 = e1 > 0.f ? e1 : SLOPE * e1;
            float e2 = esq.z + edq.z; e2 = e2 > 0.f ? e2 : SLOPE * e2;
            float e3 = esq.w + edq.w; e3 = e3 > 0.f ? e3 : SLOPE * e3;
            sw[wi][lane] = make_float4(__expf(e0), __expf(e1), __expf(e2), __expf(e3));
        }
        __syncwarp();
        const float* swf = (const float*)&sw[wi][0];
#pragma unroll 4
        for (int j = 0; j < cnt; j++) {
            int s = ss[wi][j];
            float wj = swf[j * 4 + hl];
            wsum += wj;
            uint2 hv = HH2[s * 32 + lane];
            float2 f0 = __half22float2(*(const __half2*)&hv.x);
            float2 f1 = __half22float2(*(const __half2*)&hv.y);
            a0 += wj * f0.x; a1 += wj * f0.y;
            a2 += wj * f1.x; a3 += wj * f1.y;
        }
    }

    float inv = 1.f / (wsum + 1e-16f);
    int c0 = lane * 4;
    float v0 = a0 * inv + bias[c0 + 0];
    float v1 = a1 * inv + bias[c0 + 1];
    float v2 = a2 * inv + bias[c0 + 2];
    float v3 = a3 * inv + bias[c0 + 3];
    v0 = v0 > 0.f ? v0 : expm1f(v0);
    v1 = v1 > 0.f ? v1 : expm1f(v1);
    v2 = v2 > 0.f ? v2 : expm1f(v2);
    v3 = v3 > 0.f ? v3 : expm1f(v3);
    ((float4*)g_x)[n * 32 + lane] = make_float4(v0, v1, v2, v3);
}

// ---------------- Layer-1 aggregation FUSED with layer-2 GEMM ----------------
#define AGG1F_SMEM ((FEAT * OUTC + 32 * FEAT + 32 * 32 * 4 + 32 * 32) * 4)

__global__ __launch_bounds__(1024, 2) void agg1f_kernel(
    const float* __restrict__ bias,    // b1
    const float* __restrict__ W2,
    const float* __restrict__ avs2,
    const float* __restrict__ avd2
) {
    extern __shared__ float smf[];
    float*  Ws  = smf;                                   // 20 KB
    float*  xst = smf + FEAT * OUTC;                     // 16 KB
    float4* sw  = (float4*)(xst + 32 * FEAT);            // 16 KB
    int*    ss  = (int*)(sw + 32 * 32);                  //  4 KB

    int tid = threadIdx.x;
    int wi = tid >> 5, lane = tid & 31;

    for (int i = tid; i < FEAT * OUTC; i += 1024) Ws[i] = W2[i];
    __syncthreads();

    int n = (blockIdx.x << 5) + wi;
    bool valid = (n < NNODES);
    int r0 = 0, r1 = 0;
    if (valid) { r0 = g_rowptr[n]; r1 = g_rowptr[n + 1]; }

    const float4* ES4 = (const float4*)g_es;
    float4 edq = valid ? ((const float4*)g_ed)[n] : make_float4(0.f, 0.f, 0.f, 0.f);
    int hl = lane >> 3;

    float a0 = 0.f, a1 = 0.f, a2 = 0.f, a3 = 0.f, wsum = 0.f;
    const uint2* HH2 = (const uint2*)g_hh;
    float4* swr = sw + wi * 32;
    int*    ssr = ss + wi * 32;

    for (int base = r0; base < r1; base += 32) {
        int cnt = min(32, r1 - base);
        __syncwarp();
        if (lane < cnt) {
            int s = g_csr[base + lane];
            ssr[lane] = s;
            float4 esq = ES4[s];
            float e0 = esq.x + edq.x; e0 = e0 > 0.f ? e0 : SLOPE * e0;
            float e1 = esq.y + edq.y; e1 = e1 > 0.f ? e1 : SLOPE * e1;
            float e2 = esq.z + edq.z; e2 = e2 > 0.f ? e2 : SLOPE * e2;
            float e3 = esq.w + edq.w; e3 = e3 > 0.f ? e3 : SLOPE * e3;
            swr[lane] = make_float4(__expf(e0), __expf(e1), __expf(e2), __expf(e3));
        }
        __syncwarp();
        const float* swf = (const float*)swr;
#pragma unroll 4
        for (int j = 0; j < cnt; j++) {
            int s = ssr[j];
            float wj = swf[j * 4 + hl];
            wsum += wj;
            uint2 hv = HH2[s * 32 + lane];
            float2 f0 = __half22float2(*(const __half2*)&hv.x);
            float2 f1 = __half22float2(*(const __half2*)&hv.y);
            a0 += wj * f0.x; a1 += wj * f0.y;
            a2 += wj * f1.x; a3 += wj * f1.y;
        }
    }

    float inv = 1.f / (wsum + 1e-16f);
    int c0 = lane * 4;
    float v0 = a0 * inv + bias[c0 + 0];
    float v1 = a1 * inv + bias[c0 + 1];
    float v2 = a2 * inv + bias[c0 + 2];
    float v3 = a3 * inv + bias[c0 + 3];
    v0 = v0 > 0.f ? v0 : expm1f(v0);
    v1 = v1 > 0.f ? v1 : expm1f(v1);
    v2 = v2 > 0.f ? v2 : expm1f(v2);
    v3 = v3 > 0.f ? v3 : expm1f(v3);

    float* xw = xst + wi * FEAT;
    xw[c0 + 0] = v0;
    xw[c0 + 1] = v1;
    xw[c0 + 2] = v2;
    xw[c0 + 3] = v3;
    __syncwarp();

    float acc0 = 0.f, acc1 = 0.f;
    const float4* xq = (const float4*)xw;
#pragma unroll 8
    for (int k4 = 0; k4 < FEAT / 4; k4++) {
        float4 xv = xq[k4];
        int k = k4 * 4;
        acc0 += xv.x * Ws[(k + 0) * OUTC + lane];
        acc0 += xv.y * Ws[(k + 1) * OUTC + lane];
        acc0 += xv.z * Ws[(k + 2) * OUTC + lane];
        acc0 += xv.w * Ws[(k + 3) * OUTC + lane];
        if (lane < 8) {
            acc1 += xv.x * Ws[(k + 0) * OUTC + 32 + lane];
            acc1 += xv.y * Ws[(k + 1) * OUTC + 32 + lane];
            acc1 += xv.z * Ws[(k + 2) * OUTC + 32 + lane];
            acc1 += xv.w * Ws[(k + 3) * OUTC + 32 + lane];
        }
    }

    float pes = acc0 * avs2[lane] + ((lane < 8) ? acc1 * avs2[32 + lane] : 0.f);
    float ped = acc0 * avd2[lane] + ((lane < 8) ? acc1 * avd2[32 + lane] : 0.f);
#pragma unroll
    for (int off = 16; off; off >>= 1) {
        pes += __shfl_xor_sync(0xffffffffu, pes, off);
        ped += __shfl_xor_sync(0xffffffffu, ped, off);
    }

    if (valid) {
        g_h2[n * OUTC + lane] = acc0;
        if (lane < 8) g_h2[n * OUTC + 32 + lane] = acc1;
        if (lane == 0) { g_es2[n] = pes; g_ed2[n] = ped; }
    }
}

// ---------------- Layer 2 aggregation + log_softmax ----------------
__global__ void agg2_kernel(const float* __restrict__ bias, float* __restrict__ out) {
    __shared__ float sww[8][32];
    __shared__ int   ss[8][32];
    int tid = threadIdx.x;
    int wi = tid >> 5, lane = tid & 31;
    int n = (blockIdx.x << 3) + wi;
    if (n >= NNODES) return;
    int r0 = g_rowptr[n], r1 = g_rowptr[n + 1];
    float edn = g_ed2[n];

    float acc0 = 0.f, acc1 = 0.f, wsum = 0.f;
    for (int base = r0; base < r1; base += 32) {
        int cnt = min(32, r1 - base);
        __syncwarp();
        if (lane < cnt) {
            int s = g_csr[base + lane];
            ss[wi][lane] = s;
            float e = g_es2[s] + edn;
            e = e > 0.f ? e : SLOPE * e;
            sww[wi][lane] = __expf(e);
        }
        __syncwarp();
#pragma unroll 4
        for (int j = 0; j < cnt; j++) {
            int s = ss[wi][j];
            float wj = sww[wi][j];
            wsum += wj;
            acc0 += wj * g_h2[s * OUTC + lane];
            if (lane < 8) acc1 += wj * g_h2[s * OUTC + 32 + lane];
        }
    }

    float inv = 1.f / (wsum + 1e-16f);
    float v0 = acc0 * inv + bias[lane];
    float v1 = (lane < 8) ? (acc1 * inv + bias[32 + lane]) : -1e30f;

    float mx = fmaxf(v0, v1);
#pragma unroll
    for (int off = 16; off; off >>= 1)
        mx = fmaxf(mx, __shfl_xor_sync(0xffffffffu, mx, off));

    float se = expf(v0 - mx) + ((lane < 8) ? expf(v1 - mx) : 0.f);
#pragma unroll
    for (int off = 16; off; off >>= 1)
        se += __shfl_xor_sync(0xffffffffu, se, off);

    float lse = mx + logf(se);
    out[n * OUTC + lane] = v0 - lse;
    if (lane < 8) out[n * OUTC + 32 + lane] = v1 - lse;
}

// ---------------- launch ----------------
extern "C" void kernel_launch(void* const* d_in, const int* in_sizes, int n_in,
                              void* d_out, int out_size) {
    const float* x   = (const float*)d_in[0];
    const int*   ei  = (const int*)d_in[1];
    const float* W0  = (const float*)d_in[2];
    const float* as0 = (const float*)d_in[3];
    const float* ad0 = (const float*)d_in[4];
    const float* b0  = (const float*)d_in[5];
    const float* W1  = (const float*)d_in[6];
    const float* as1 = (const float*)d_in[7];
    const float* ad1 = (const float*)d_in[8];
    const float* b1  = (const float*)d_in[9];
    const float* W2  = (const float*)d_in[10];
    const float* as2 = (const float*)d_in[11];
    const float* ad2 = (const float*)d_in[12];
    const float* b2  = (const float*)d_in[13];
    float* out = (float*)d_out;

    int E = in_sizes[1] / 2;
    if (E + NNODES > MAXE) return;

    const int GSM = (FEAT * FEAT + 64 * FEAT) * 4;  // 96 KB dynamic smem
    cudaFuncSetAttribute(gemm128_kernel, cudaFuncAttributeMaxDynamicSharedMemorySize, GSM);
    cudaFuncSetAttribute(agg1f_kernel, cudaFuncAttributeMaxDynamicSharedMemorySize, AGG1F_SMEM);

    // Second stream for the CSR build (independent of layer-0 GEMM).
    // Created per call: host-side only; replays execute the captured graph,
    // so this never costs timed microseconds. Non-blocking to avoid legacy-
    // stream implicit serialization during capture.
    cudaStream_t s2;
    cudaStreamCreateWithFlags(&s2, cudaStreamNonBlocking);
    cudaEvent_t evFork, evJoin;
    cudaEventCreateWithFlags(&evFork, cudaEventDisableTiming);
    cudaEventCreateWithFlags(&evJoin, cudaEventDisableTiming);

    cudaEventRecord(evFork, 0);
    cudaStreamWaitEvent(s2, evFork, 0);

    // CSR build on s2 (2-level scan folded into rowptr)
    zero_cnt_kernel<<<(NNODES + 255) / 256, 256, 0, s2>>>();
    count_kernel<<<(E + 255) / 256, 256, 0, s2>>>(ei, E);
    blocksum_kernel<<<NB, 256, 0, s2>>>();
    rowptr_kernel<<<NB, 256, 0, s2>>>();
    scatter_kernel<<<(E + 255) / 256, 256, 0, s2>>>(ei, E);
    cudaEventRecord(evJoin, s2);

    int gemm_grid = (NNODES + 63) / 64;
    int agg_grid  = (NNODES + 7) / 8;
    int agg1f_grid = (NNODES + 31) / 32;

    // layer-0 GEMM overlaps the CSR build
    gemm128_kernel<<<gemm_grid, 256, GSM>>>(x, 0, W0, as0, ad0);

    // join: aggregation needs CSR + gemm0
    cudaStreamWaitEvent(0, evJoin, 0);

    agg_kernel<<<agg_grid, 256>>>(b0);
    gemm128_kernel<<<gemm_grid, 256, GSM>>>(nullptr, 1, W1, as1, ad1);
    agg1f_kernel<<<agg1f_grid, 1024, AGG1F_SMEM>>>(b1, W2, as2, ad2);
    agg2_kernel<<<agg_grid, 256>>>(b2, out);
}